// round 2
// baseline (speedup 1.0000x reference)
#include <cuda_runtime.h>
#include <math.h>

#define NN    32768
#define EMBD  512
#define NH    4
#define OUTD  2048
#define EE    131072
#define ET    (EE + NN)     // edges + self loops = 163840
#define NB    32
#define HIDD  32

// ---------------- scratch (device globals; no allocation allowed) ----------
__device__ float    g_x  [NN * EMBD];          // 64 MB
__device__ float    g_h  [(size_t)NN * OUTD];  // 256 MB
__device__ float    g_gat[(size_t)NN * OUTD];  // 256 MB
__device__ float    g_as [NN * NH];
__device__ float    g_ad [NN * NH];
__device__ unsigned g_amax[NN * NH];           // ordered-uint encoded float max
__device__ float    g_den[NN * NH];
__device__ float    g_w  [ET * NH];            // edge logits -> exp weights
__device__ int      g_cnt[NN];
__device__ int      g_off[NN + 1];
__device__ int      g_cur[NN];
__device__ int      g_csr[ET];
__device__ int      g_bstart[NB + 1];
__device__ float    g_pool[NB * 2 * OUTD];     // [b][0:2048]=sum, [2048:4096]=max

// ordered-uint encoding for float atomicMax (handles negatives)
__device__ __forceinline__ unsigned encf(float f) {
    unsigned u = __float_as_uint(f);
    return (u & 0x80000000u) ? ~u : (u | 0x80000000u);
}
__device__ __forceinline__ float decf(unsigned u) {
    return __uint_as_float((u & 0x80000000u) ? (u ^ 0x80000000u) : ~u);
}
#define ENC_NEGINF 0x007FFFFFu   // encf(-inf)

// ---------------- init ------------------------------------------------------
__global__ void k_init() {
    int i = blockIdx.x * blockDim.x + threadIdx.x;
    if (i < NN * NH) { g_amax[i] = ENC_NEGINF; g_den[i] = 0.f; }
    if (i < NN)      { g_cnt[i] = 0; }
}

// ---------------- SGEMM 128x128x8, 256 threads, 8x8 microtile ---------------
// A [M,K] row-major (optionally row-gathered), B [K,Np] row-major, C [M,Np]
template<int GATHER>
__global__ __launch_bounds__(256)
void k_sgemm(const float* __restrict__ A, const float* __restrict__ Bm,
             const float* __restrict__ bias, float* __restrict__ C,
             const int* __restrict__ idx, int M, int Np, int K)
{
    __shared__ float As[8][128];
    __shared__ float Bs[8][128];
    const int tid  = threadIdx.x;
    const int brow = blockIdx.y * 128;
    const int bcol = blockIdx.x * 128;
    const int tx = tid & 15, ty = tid >> 4;

    // global-load assignments
    const int arow = tid >> 1, ak = (tid & 1) * 4;
    const int brk  = tid >> 5, bc4 = (tid & 31) * 4;
    int grow = brow + arow;
    if (GATHER) grow = idx[grow];
    const float* Aptr = A + (size_t)grow * K + ak;
    const float* Bptr = Bm + (size_t)brk * Np + bcol + bc4;

    float acc[8][8];
    #pragma unroll
    for (int i = 0; i < 8; i++)
        #pragma unroll
        for (int j = 0; j < 8; j++) acc[i][j] = 0.f;

    for (int k0 = 0; k0 < K; k0 += 8) {
        float4 a4 = *(const float4*)(Aptr + k0);
        float4 b4 = *(const float4*)(Bptr + (size_t)k0 * Np);
        As[ak + 0][arow] = a4.x; As[ak + 1][arow] = a4.y;
        As[ak + 2][arow] = a4.z; As[ak + 3][arow] = a4.w;
        *(float4*)&Bs[brk][bc4] = b4;
        __syncthreads();
        #pragma unroll
        for (int kk = 0; kk < 8; kk++) {
            float af[8], bf[8];
            *(float4*)&af[0] = *(const float4*)&As[kk][ty * 8];
            *(float4*)&af[4] = *(const float4*)&As[kk][ty * 8 + 4];
            *(float4*)&bf[0] = *(const float4*)&Bs[kk][tx * 8];
            *(float4*)&bf[4] = *(const float4*)&Bs[kk][tx * 8 + 4];
            #pragma unroll
            for (int i = 0; i < 8; i++)
                #pragma unroll
                for (int j = 0; j < 8; j++)
                    acc[i][j] = fmaf(af[i], bf[j], acc[i][j]);
        }
        __syncthreads();
    }

    float bv[8];
    #pragma unroll
    for (int j = 0; j < 8; j++) bv[j] = bias ? bias[bcol + tx * 8 + j] : 0.f;

    #pragma unroll
    for (int i = 0; i < 8; i++) {
        float* crow = C + (size_t)(brow + ty * 8 + i) * Np + bcol + tx * 8;
        #pragma unroll
        for (int j = 0; j < 8; j++) crow[j] = acc[i][j] + bv[j];
    }
}

// ---------------- per-node attention dots a_src/a_dst -----------------------
__global__ __launch_bounds__(256)
void k_attn_node(const float* __restrict__ att_s, const float* __restrict__ att_d)
{
    const int n = blockIdx.x, t = threadIdx.x;
    const float* hrow = &g_h[(size_t)n * OUTD];
    float ps[4] = {0, 0, 0, 0}, pd[4] = {0, 0, 0, 0};
    #pragma unroll
    for (int j = 0; j < 8; j++) {
        int col = t + j * 256;
        int hd  = j >> 1;          // 512 cols per head, 256 per j
        float v = hrow[col];
        ps[hd] = fmaf(v, att_s[col], ps[hd]);
        pd[hd] = fmaf(v, att_d[col], pd[hd]);
    }
    __shared__ float rs[256], rd[256];
    for (int hd = 0; hd < 4; hd++) {
        rs[t] = ps[hd]; rd[t] = pd[hd];
        __syncthreads();
        for (int o = 128; o > 0; o >>= 1) {
            if (t < o) { rs[t] += rs[t + o]; rd[t] += rd[t + o]; }
            __syncthreads();
        }
        if (t == 0) { g_as[n * NH + hd] = rs[0]; g_ad[n * NH + hd] = rd[0]; }
        __syncthreads();
    }
}

// ---------------- edge logits + segment max + degree counts -----------------
__global__ void k_edge_logits(const int* __restrict__ src, const int* __restrict__ dst)
{
    int e = blockIdx.x * blockDim.x + threadIdx.x;
    if (e >= ET) return;
    int s = (e < EE) ? src[e] : (e - EE);
    int d = (e < EE) ? dst[e] : (e - EE);
    #pragma unroll
    for (int h = 0; h < NH; h++) {
        float v = g_as[s * NH + h] + g_ad[d * NH + h];
        v = (v > 0.f) ? v : 0.2f * v;          // leaky_relu slope 0.2
        g_w[e * NH + h] = v;
        atomicMax(&g_amax[d * NH + h], encf(v));
    }
    atomicAdd(&g_cnt[d], 1);
}

// ---------------- edge exp + denom ------------------------------------------
__global__ void k_edge_exp(const int* __restrict__ src, const int* __restrict__ dst)
{
    int e = blockIdx.x * blockDim.x + threadIdx.x;
    if (e >= ET) return;
    int d = (e < EE) ? dst[e] : (e - EE);
    #pragma unroll
    for (int h = 0; h < NH; h++) {
        float m = decf(g_amax[d * NH + h]);
        float w = __expf(g_w[e * NH + h] - m);
        g_w[e * NH + h] = w;
        atomicAdd(&g_den[d * NH + h], w);
    }
}

// ---------------- exclusive scan of counts (1 block, 1024 threads) ----------
__global__ __launch_bounds__(1024)
void k_scan()
{
    __shared__ int sm[1024];
    const int t = threadIdx.x, base = t * 32;
    int s = 0;
    for (int i = 0; i < 32; i++) s += g_cnt[base + i];
    sm[t] = s;
    __syncthreads();
    for (int o = 1; o < 1024; o <<= 1) {
        int v = (t >= o) ? sm[t - o] : 0;
        __syncthreads();
        sm[t] += v;
        __syncthreads();
    }
    int run = sm[t] - s;   // exclusive prefix of this thread's chunk
    for (int i = 0; i < 32; i++) {
        g_off[base + i] = run;
        g_cur[base + i] = run;
        run += g_cnt[base + i];
    }
    if (t == 1023) g_off[NN] = sm[1023];
}

// ---------------- scatter edge ids into CSR ---------------------------------
__global__ void k_scatter(const int* __restrict__ dst)
{
    int e = blockIdx.x * blockDim.x + threadIdx.x;
    if (e >= ET) return;
    int d = (e < EE) ? dst[e] : (e - EE);
    int pos = atomicAdd(&g_cur[d], 1);
    g_csr[pos] = e;
}

// ---------------- aggregation: out[d] = sum_e w_e * h[src_e]; epilogue ------
__global__ __launch_bounds__(256)
void k_aggregate(const int* __restrict__ src, const float* __restrict__ bias_gat)
{
    const int d = blockIdx.x, t = threadIdx.x;
    float acc[8];
    #pragma unroll
    for (int j = 0; j < 8; j++) acc[j] = 0.f;

    const int beg = g_off[d], end = g_off[d + 1];
    for (int p = beg; p < end; p++) {
        int e = g_csr[p];
        int s = (e < EE) ? src[e] : (e - EE);
        float w0 = g_w[e * 4 + 0], w1 = g_w[e * 4 + 1];
        float w2 = g_w[e * 4 + 2], w3 = g_w[e * 4 + 3];
        const float* hrow = &g_h[(size_t)s * OUTD];
        #pragma unroll
        for (int j = 0; j < 8; j++) {
            int col = t + j * 256;
            float wv = (j < 2) ? w0 : (j < 4) ? w1 : (j < 6) ? w2 : w3;
            acc[j] = fmaf(wv, hrow[col], acc[j]);
        }
    }
    float dn[4];
    #pragma unroll
    for (int h = 0; h < 4; h++) dn[h] = 1.f / (g_den[d * 4 + h] + 1e-16f);
    float* orow = &g_gat[(size_t)d * OUTD];
    #pragma unroll
    for (int j = 0; j < 8; j++) {
        int col = t + j * 256;
        float v = acc[j] * dn[j >> 1] + bias_gat[col];
        orow[col] = (v > 0.f) ? v : 0.01f * v;   // outer leaky_relu (default 0.01)
    }
}

// ---------------- batch segment bounds (batch sorted) -----------------------
__global__ void k_bstart(const int* __restrict__ batch)
{
    int t = threadIdx.x;
    if (t > NB) return;
    int lo = 0, hi = NN;
    while (lo < hi) { int mid = (lo + hi) >> 1; if (batch[mid] < t) lo = mid + 1; else hi = mid; }
    g_bstart[t] = lo;
}

// ---------------- pooling: per-graph sum + max ------------------------------
__global__ __launch_bounds__(256)
void k_pool()
{
    const int b = blockIdx.y;
    const int col = blockIdx.x * 256 + threadIdx.x;
    const int beg = g_bstart[b], end = g_bstart[b + 1];
    float s = 0.f, mx = -INFINITY;
    int n = beg;
    for (; n + 4 <= end; n += 4) {
        float v0 = g_gat[(size_t)(n + 0) * OUTD + col];
        float v1 = g_gat[(size_t)(n + 1) * OUTD + col];
        float v2 = g_gat[(size_t)(n + 2) * OUTD + col];
        float v3 = g_gat[(size_t)(n + 3) * OUTD + col];
        s += v0 + v1 + v2 + v3;
        mx = fmaxf(mx, fmaxf(fmaxf(v0, v1), fmaxf(v2, v3)));
    }
    for (; n < end; n++) {
        float v = g_gat[(size_t)n * OUTD + col];
        s += v; mx = fmaxf(mx, v);
    }
    g_pool[b * 4096 + col]        = s;
    g_pool[b * 4096 + 2048 + col] = mx;
}

// ---------------- final MLPs ------------------------------------------------
__global__ __launch_bounds__(256)
void k_mlp(const float* __restrict__ W1r, const float* __restrict__ b1r,
           const float* __restrict__ W2r, const float* __restrict__ b2r,
           const float* __restrict__ W1m, const float* __restrict__ b1m,
           const float* __restrict__ W2m, const float* __restrict__ b2m,
           float* __restrict__ out)
{
    __shared__ float g[4096];
    __shared__ float hid[2][HIDD];
    const int b = blockIdx.x, t = threadIdx.x;
    const float inv = 1.f / fmaxf((float)(g_bstart[b + 1] - g_bstart[b]), 1.f);
    for (int i = t; i < 4096; i += 256) {
        float v = g_pool[b * 4096 + i];
        g[i] = (i < 2048) ? v * inv : v;
    }
    __syncthreads();
    const int warp = t >> 5, lane = t & 31;
    for (int p = warp; p < 64; p += 8) {
        int task = p >> 5, j = p & 31;
        const float* W1 = task ? W1m : W1r;
        const float* b1 = task ? b1m : b1r;
        float s = 0.f;
        for (int k = lane; k < 4096; k += 32) s = fmaf(g[k], W1[k * HIDD + j], s);
        #pragma unroll
        for (int o = 16; o > 0; o >>= 1) s += __shfl_down_sync(0xffffffff, s, o);
        if (lane == 0) hid[task][j] = fmaxf(s + b1[j], 0.f);
    }
    __syncthreads();
    if (t < 2) {
        const float* W2 = t ? W2m : W2r;
        float o = t ? b2m[0] : b2r[0];
        #pragma unroll
        for (int j = 0; j < HIDD; j++) o = fmaf(hid[t][j], W2[j], o);
        out[t * NB + b] = o;
    }
}

// ---------------- launch ----------------------------------------------------
extern "C" void kernel_launch(void* const* d_in, const int* in_sizes, int n_in,
                              void* d_out, int out_size)
{
    const int*   code  = (const int*)d_in[0];
    const int*   ei    = (const int*)d_in[1];
    const int*   batch = (const int*)d_in[2];
    const float* emb   = (const float*)d_in[3];
    const float* Wf    = (const float*)d_in[4];
    const float* bf    = (const float*)d_in[5];
    const float* Wg    = (const float*)d_in[6];
    const float* atts  = (const float*)d_in[7];
    const float* attd  = (const float*)d_in[8];
    const float* bg    = (const float*)d_in[9];
    const float* W1r   = (const float*)d_in[10];
    const float* b1r   = (const float*)d_in[11];
    const float* W2r   = (const float*)d_in[12];
    const float* b2r   = (const float*)d_in[13];
    const float* W1m   = (const float*)d_in[14];
    const float* b1m   = (const float*)d_in[15];
    const float* W2m   = (const float*)d_in[16];
    const float* b2m   = (const float*)d_in[17];
    float* out = (float*)d_out;

    const int* src = ei;
    const int* dst = ei + EE;

    float* gx;  cudaGetSymbolAddress((void**)&gx,  g_x);
    float* gh;  cudaGetSymbolAddress((void**)&gh,  g_h);

    k_init<<<(NN * NH + 255) / 256, 256>>>();

    // x = emb[code] @ W_feat + b_feat     (M=32768, N=512, K=512)
    k_sgemm<1><<<dim3(EMBD / 128, NN / 128), 256>>>(emb, Wf, bf, gx, code, NN, EMBD, EMBD);

    // h = x @ W_gat                        (M=32768, N=2048, K=512)
    k_sgemm<0><<<dim3(OUTD / 128, NN / 128), 256>>>(gx, Wg, nullptr, gh, nullptr, NN, OUTD, EMBD);

    k_attn_node<<<NN, 256>>>(atts, attd);
    k_edge_logits<<<(ET + 255) / 256, 256>>>(src, dst);
    k_edge_exp<<<(ET + 255) / 256, 256>>>(src, dst);
    k_scan<<<1, 1024>>>();
    k_scatter<<<(ET + 255) / 256, 256>>>(dst);
    k_aggregate<<<NN, 256>>>(src, bg);
    k_bstart<<<1, 64>>>(batch);
    k_pool<<<dim3(OUTD / 256, NB), 256>>>();
    k_mlp<<<NB, 256>>>(W1r, b1r, W2r, b2r, W1m, b1m, W2m, b2m, out);
}

// round 5
// speedup vs baseline: 1.6758x; 1.6758x over previous
#include <cuda_runtime.h>
#include <cuda_bf16.h>
#include <math.h>
#include <cstdint>

#define NN    32768
#define EMBD  512
#define NH    4
#define OUTD  2048
#define EE    131072
#define ET    (EE + NN)     // edges + self loops = 163840
#define NB    32
#define HIDD  32

// GEMM tiling: CTA 128x128, K-step 32, 8 warps (2 row x 4 col), warp tile 64x32
#define BM 128
#define BN 128
#define BK 32
#define KK 512
#define NSTEP (KK / BK)        // 16
#define STRIDE 40              // padded smem row (bf16 elems): 80B, conflict-free
#define MAT (128 * STRIDE)     // elems per matrix tile buffer
#define STAGE_ELEMS (4 * MAT)  // Ah, Al, Bh, Bl
#define GEMM_DYN (2 * STAGE_ELEMS * 2)   // bytes (2 stages, bf16)

// ---------------- scratch (device globals; no allocation allowed) ----------
__device__ __nv_bfloat16 g_ah[(size_t)NN * EMBD];   // gathered emb, hi
__device__ __nv_bfloat16 g_al[(size_t)NN * EMBD];   // gathered emb, lo
__device__ __nv_bfloat16 g_xh[(size_t)NN * EMBD];   // x after feat linear, hi
__device__ __nv_bfloat16 g_xl[(size_t)NN * EMBD];
__device__ __nv_bfloat16 g_wfh[EMBD * EMBD];        // W_feat^T  [512,512] K-major
__device__ __nv_bfloat16 g_wfl[EMBD * EMBD];
__device__ __nv_bfloat16 g_wgh[(size_t)OUTD * EMBD];// W_gat^T   [2048,512] K-major
__device__ __nv_bfloat16 g_wgl[(size_t)OUTD * EMBD];
__device__ float    g_h  [(size_t)NN * OUTD];       // 256 MB
__device__ float    g_gat[(size_t)NN * OUTD];       // 256 MB
__device__ float    g_as [NN * NH];
__device__ float    g_ad [NN * NH];
__device__ unsigned g_amax[NN * NH];
__device__ float    g_den[NN * NH];
__device__ float    g_w  [ET * NH];
__device__ int      g_cnt[NN];
__device__ int      g_off[NN + 1];
__device__ int      g_cur[NN];
__device__ int      g_csr[ET];
__device__ int      g_bstart[NB + 1];
__device__ float    g_pool[NB * 2 * OUTD];

// ---------------- helpers ----------------------------------------------------
__device__ __forceinline__ uint32_t smem_u32(const void* p) {
    uint32_t a;
    asm("{ .reg .u64 t; cvta.to.shared.u64 t, %1; cvt.u32.u64 %0, t; }" : "=r"(a) : "l"(p));
    return a;
}
#define CP16(s, g) \
    asm volatile("cp.async.cg.shared.global [%0], [%1], 16;" :: "r"(s), "l"(g))
#define CP_COMMIT() asm volatile("cp.async.commit_group;" ::: "memory")
#define CP_WAIT1()  asm volatile("cp.async.wait_group 1;" ::: "memory")
#define CP_WAIT0()  asm volatile("cp.async.wait_group 0;" ::: "memory")
#define LDX4(r, a) \
    asm volatile("ldmatrix.sync.aligned.m8n8.x4.shared.b16 {%0,%1,%2,%3}, [%4];" \
        : "=r"((r)[0]), "=r"((r)[1]), "=r"((r)[2]), "=r"((r)[3]) : "r"(a))
#define MMA(d, a, b0, b1) \
    asm volatile("mma.sync.aligned.m16n8k16.row.col.f32.bf16.bf16.f32 " \
        "{%0,%1,%2,%3},{%4,%5,%6,%7},{%8,%9},{%0,%1,%2,%3};" \
        : "+f"((d)[0]), "+f"((d)[1]), "+f"((d)[2]), "+f"((d)[3]) \
        : "r"((a)[0]), "r"((a)[1]), "r"((a)[2]), "r"((a)[3]), "r"(b0), "r"(b1))

__device__ __forceinline__ void split2(float v, __nv_bfloat16& h, __nv_bfloat16& l) {
    h = __float2bfloat16(v);
    l = __float2bfloat16(v - __bfloat162float(h));
}
__device__ __forceinline__ unsigned encf(float f) {
    unsigned u = __float_as_uint(f);
    return (u & 0x80000000u) ? ~u : (u | 0x80000000u);
}
__device__ __forceinline__ float decf(unsigned u) {
    return __uint_as_float((u & 0x80000000u) ? (u ^ 0x80000000u) : ~u);
}
#define ENC_NEGINF 0x007FFFFFu

// ---------------- init ------------------------------------------------------
__global__ void k_init() {
    int i = blockIdx.x * blockDim.x + threadIdx.x;
    if (i < NN * NH) { g_amax[i] = ENC_NEGINF; g_den[i] = 0.f; g_as[i] = 0.f; g_ad[i] = 0.f; }
    if (i < NN)      { g_cnt[i] = 0; }
}

// ---------------- prep: gather emb rows + split to bf16 hi/lo ---------------
__global__ __launch_bounds__(256) void k_prep_emb(const int* __restrict__ code,
                                                  const float* __restrict__ emb)
{
    int id = blockIdx.x * 256 + threadIdx.x;        // NN*128 ids, 4 elems each
    int m = id >> 7, c4 = (id & 127) << 2;
    float4 v = *(const float4*)&emb[(size_t)code[m] * EMBD + c4];
    __nv_bfloat16 h[4], l[4];
    split2(v.x, h[0], l[0]); split2(v.y, h[1], l[1]);
    split2(v.z, h[2], l[2]); split2(v.w, h[3], l[3]);
    *(uint2*)&g_ah[(size_t)m * EMBD + c4] = *(uint2*)h;
    *(uint2*)&g_al[(size_t)m * EMBD + c4] = *(uint2*)l;
}

// ---------------- prep: W [K=512, Ncols] -> W^T hi/lo [Ncols, 512] ----------
__global__ __launch_bounds__(256) void k_prep_w(const float* __restrict__ W,
                                                __nv_bfloat16* __restrict__ Th,
                                                __nv_bfloat16* __restrict__ Tl, int Ncols)
{
    int id = blockIdx.x * 256 + threadIdx.x;
    if (id >= Ncols * EMBD) return;
    int n = id >> 9, k = id & 511;
    float v = W[(size_t)k * Ncols + n];
    __nv_bfloat16 h, l; split2(v, h, l);
    Th[(size_t)n * EMBD + k] = h;
    Tl[(size_t)n * EMBD + k] = l;
}

// ---------------- HMMA split-bf16 GEMM ---------------------------------------
// D[M,N] = (Ah+Al)[M,K] @ (Bh+Bl)^T  where B stored [N,K] K-major
// EPI==1: out = D + bias -> split bf16 (outH, outL)
// EPI==2: out = D fp32 -> outF, plus fused a_src/a_dst dot partials
template<int EPI>
__global__ __launch_bounds__(256, 1)
void k_gemm(const __nv_bfloat16* __restrict__ Ah, const __nv_bfloat16* __restrict__ Al,
            const __nv_bfloat16* __restrict__ Bh, const __nv_bfloat16* __restrict__ Bl,
            const float* __restrict__ bias,
            const float* __restrict__ atts, const float* __restrict__ attd,
            float* __restrict__ outF,
            __nv_bfloat16* __restrict__ outH, __nv_bfloat16* __restrict__ outL,
            int Nout)
{
    extern __shared__ __nv_bfloat16 sm[];
    __shared__ float s_v1[BN], s_v2[BN], s_ps[BM], s_pd[BM];

    const int tid  = threadIdx.x;
    const int lane = tid & 31, wid = tid >> 5;
    const int wr = wid >> 2, wc = wid & 3;         // warp 64-row block, 32-col block
    const int brow = blockIdx.y * BM;
    const int bcol = blockIdx.x * BN;

    if (tid < BN) {
        if (EPI == 1) s_v1[tid] = bias[bcol + tid];
        else {
            s_v1[tid] = atts[bcol + tid];
            s_v2[tid] = attd[bcol + tid];
            s_ps[tid] = 0.f; s_pd[tid] = 0.f;
        }
    }

    const uint32_t sbase = smem_u32(sm);
    // stage s, matrix m (0=Ah 1=Al 2=Bh 3=Bl) at sbase + (s*4+m)*MAT*2 bytes

    // global load assignment: 2 iters of (row = i>>2, seg = i&3), 4 cp.async each
    auto load_stage = [&](int st, int k0) {
        const uint32_t so = sbase + st * (STAGE_ELEMS * 2);
        #pragma unroll
        for (int it = 0; it < 2; it++) {
            int i = tid + it * 256;
            int row = i >> 2, seg = i & 3;
            uint32_t sofs = (uint32_t)(row * STRIDE + seg * 8) * 2;
            size_t ga = (size_t)(brow + row) * KK + k0 * BK + seg * 8;
            size_t gb = (size_t)(bcol + row) * KK + k0 * BK + seg * 8;
            CP16(so + 0 * MAT * 2 + sofs, Ah + ga);
            CP16(so + 1 * MAT * 2 + sofs, Al + ga);
            CP16(so + 2 * MAT * 2 + sofs, Bh + gb);
            CP16(so + 3 * MAT * 2 + sofs, Bl + gb);
        }
    };

    float d[4][4][4];
    #pragma unroll
    for (int mt = 0; mt < 4; mt++)
        #pragma unroll
        for (int nt = 0; nt < 4; nt++)
            #pragma unroll
            for (int j = 0; j < 4; j++) d[mt][nt][j] = 0.f;

    // lane-fixed address pieces (bytes)
    const uint32_t a_lane = (uint32_t)((wr * 64 + (lane & 15)) * STRIDE) * 2 + ((lane >> 4) * 8) * 2;
    const uint32_t b_lane = (uint32_t)((wc * 32 + ((lane >> 4) & 1) * 8 + (lane & 7)) * STRIDE) * 2
                          + (((lane >> 3) & 1) * 8) * 2;

    load_stage(0, 0);
    CP_COMMIT();

    for (int k0 = 0; k0 < NSTEP; k0++) {
        const int st = k0 & 1;
        if (k0 + 1 < NSTEP) { load_stage(st ^ 1, k0 + 1); CP_COMMIT(); CP_WAIT1(); }
        else                { CP_WAIT0(); }
        __syncthreads();

        const uint32_t so = sbase + st * (STAGE_ELEMS * 2);
        const uint32_t aH = so + 0 * MAT * 2 + a_lane;
        const uint32_t aL = so + 1 * MAT * 2 + a_lane;
        const uint32_t bH = so + 2 * MAT * 2 + b_lane;
        const uint32_t bL = so + 3 * MAT * 2 + b_lane;

        #pragma unroll
        for (int ks = 0; ks < 2; ks++) {
            const uint32_t ko = ks * 16 * 2;   // k16 sub-step byte offset
            uint32_t ah[4][4], al[4][4], bh[2][4], bl[2][4];
            #pragma unroll
            for (int mt = 0; mt < 4; mt++) LDX4(ah[mt], aH + mt * 16 * STRIDE * 2 + ko);
            #pragma unroll
            for (int np = 0; np < 2; np++) LDX4(bh[np], bH + np * 16 * STRIDE * 2 + ko);
            #pragma unroll
            for (int mt = 0; mt < 4; mt++)
                #pragma unroll
                for (int nt = 0; nt < 4; nt++)
                    MMA(d[mt][nt], ah[mt], bh[nt >> 1][(nt & 1) * 2], bh[nt >> 1][(nt & 1) * 2 + 1]);
            #pragma unroll
            for (int mt = 0; mt < 4; mt++) LDX4(al[mt], aL + mt * 16 * STRIDE * 2 + ko);
            #pragma unroll
            for (int mt = 0; mt < 4; mt++)
                #pragma unroll
                for (int nt = 0; nt < 4; nt++)
                    MMA(d[mt][nt], al[mt], bh[nt >> 1][(nt & 1) * 2], bh[nt >> 1][(nt & 1) * 2 + 1]);
            #pragma unroll
            for (int np = 0; np < 2; np++) LDX4(bl[np], bL + np * 16 * STRIDE * 2 + ko);
            #pragma unroll
            for (int mt = 0; mt < 4; mt++)
                #pragma unroll
                for (int nt = 0; nt < 4; nt++)
                    MMA(d[mt][nt], ah[mt], bl[nt >> 1][(nt & 1) * 2], bl[nt >> 1][(nt & 1) * 2 + 1]);
        }
        __syncthreads();
    }

    // ---------------- epilogue ----------------
    const int gid = lane >> 2, tig = lane & 3;
    float ps0[4] = {0,0,0,0}, ps1[4] = {0,0,0,0};
    float pd0[4] = {0,0,0,0}, pd1[4] = {0,0,0,0};

    #pragma unroll
    for (int mt = 0; mt < 4; mt++) {
        const int r0 = wr * 64 + mt * 16 + gid;
        #pragma unroll
        for (int nt = 0; nt < 4; nt++) {
            const int c = wc * 32 + nt * 8 + tig * 2;
            float v0 = d[mt][nt][0], v1 = d[mt][nt][1];
            float v2 = d[mt][nt][2], v3 = d[mt][nt][3];
            if (EPI == 1) {
                __nv_bfloat16 h0, l0, h1, l1;
                split2(v0 + s_v1[c], h0, l0); split2(v1 + s_v1[c + 1], h1, l1);
                __nv_bfloat162 hp; hp.x = h0; hp.y = h1;
                __nv_bfloat162 lp; lp.x = l0; lp.y = l1;
                *(__nv_bfloat162*)(outH + (size_t)(brow + r0) * Nout + bcol + c) = hp;
                *(__nv_bfloat162*)(outL + (size_t)(brow + r0) * Nout + bcol + c) = lp;
                split2(v2 + s_v1[c], h0, l0); split2(v3 + s_v1[c + 1], h1, l1);
                hp.x = h0; hp.y = h1; lp.x = l0; lp.y = l1;
                *(__nv_bfloat162*)(outH + (size_t)(brow + r0 + 8) * Nout + bcol + c) = hp;
                *(__nv_bfloat162*)(outL + (size_t)(brow + r0 + 8) * Nout + bcol + c) = lp;
            } else {
                float2 f01 = make_float2(v0, v1);
                float2 f23 = make_float2(v2, v3);
                *(float2*)(outF + (size_t)(brow + r0) * Nout + bcol + c) = f01;
                *(float2*)(outF + (size_t)(brow + r0 + 8) * Nout + bcol + c) = f23;
                float w0 = s_v1[c], w1 = s_v1[c + 1];
                float u0 = s_v2[c], u1 = s_v2[c + 1];
                ps0[mt] = fmaf(v0, w0, fmaf(v1, w1, ps0[mt]));
                ps1[mt] = fmaf(v2, w0, fmaf(v3, w1, ps1[mt]));
                pd0[mt] = fmaf(v0, u0, fmaf(v1, u1, pd0[mt]));
                pd1[mt] = fmaf(v2, u0, fmaf(v3, u1, pd1[mt]));
            }
        }
    }
    if (EPI == 2) {
        #pragma unroll
        for (int mt = 0; mt < 4; mt++) {
            const int r0 = wr * 64 + mt * 16 + gid;
            atomicAdd(&s_ps[r0], ps0[mt]);     atomicAdd(&s_ps[r0 + 8], ps1[mt]);
            atomicAdd(&s_pd[r0], pd0[mt]);     atomicAdd(&s_pd[r0 + 8], pd1[mt]);
        }
        __syncthreads();
        if (tid < BM) {
            const int head = bcol >> 9;        // 128-col tile lies in one 512-col head
            atomicAdd(&g_as[(brow + tid) * NH + head], s_ps[tid]);
            atomicAdd(&g_ad[(brow + tid) * NH + head], s_pd[tid]);
        }
    }
}

// ---------------- edge logits + segment max + degree counts -----------------
__global__ void k_edge_logits(const int* __restrict__ src, const int* __restrict__ dst)
{
    int e = blockIdx.x * blockDim.x + threadIdx.x;
    if (e >= ET) return;
    int s = (e < EE) ? src[e] : (e - EE);
    int d = (e < EE) ? dst[e] : (e - EE);
    #pragma unroll
    for (int h = 0; h < NH; h++) {
        float v = g_as[s * NH + h] + g_ad[d * NH + h];
        v = (v > 0.f) ? v : 0.2f * v;
        g_w[e * NH + h] = v;
        atomicMax(&g_amax[d * NH + h], encf(v));
    }
    atomicAdd(&g_cnt[d], 1);
}

__global__ void k_edge_exp(const int* __restrict__ src, const int* __restrict__ dst)
{
    int e = blockIdx.x * blockDim.x + threadIdx.x;
    if (e >= ET) return;
    int d = (e < EE) ? dst[e] : (e - EE);
    #pragma unroll
    for (int h = 0; h < NH; h++) {
        float m = decf(g_amax[d * NH + h]);
        float w = __expf(g_w[e * NH + h] - m);
        g_w[e * NH + h] = w;
        atomicAdd(&g_den[d * NH + h], w);
    }
}

// ---------------- exclusive scan of counts ----------------------------------
__global__ __launch_bounds__(1024) void k_scan()
{
    __shared__ int sm[1024];
    const int t = threadIdx.x, base = t * 32;
    int s = 0;
    for (int i = 0; i < 32; i++) s += g_cnt[base + i];
    sm[t] = s;
    __syncthreads();
    for (int o = 1; o < 1024; o <<= 1) {
        int v = (t >= o) ? sm[t - o] : 0;
        __syncthreads();
        sm[t] += v;
        __syncthreads();
    }
    int run = sm[t] - s;
    for (int i = 0; i < 32; i++) {
        g_off[base + i] = run;
        g_cur[base + i] = run;
        run += g_cnt[base + i];
    }
    if (t == 1023) g_off[NN] = sm[1023];
}

__global__ void k_scatter(const int* __restrict__ dst)
{
    int e = blockIdx.x * blockDim.x + threadIdx.x;
    if (e >= ET) return;
    int d = (e < EE) ? dst[e] : (e - EE);
    int pos = atomicAdd(&g_cur[d], 1);
    g_csr[pos] = e;
}

// ---------------- aggregation ------------------------------------------------
__global__ __launch_bounds__(256)
void k_aggregate(const int* __restrict__ src, const float* __restrict__ bias_gat)
{
    const int d = blockIdx.x, t = threadIdx.x;
    const int c0 = t * 8;
    const int hd = t >> 6;
    float4 a0 = {0,0,0,0}, a1 = {0,0,0,0};
    const int beg = g_off[d], end = g_off[d + 1];
    for (int p = beg; p < end; p++) {
        int e = g_csr[p];
        int s = (e < EE) ? src[e] : (e - EE);
        float w = g_w[e * NH + hd];
        const float4* hr = (const float4*)&g_h[(size_t)s * OUTD + c0];
        float4 v0 = hr[0], v1 = hr[1];
        a0.x = fmaf(w, v0.x, a0.x); a0.y = fmaf(w, v0.y, a0.y);
        a0.z = fmaf(w, v0.z, a0.z); a0.w = fmaf(w, v0.w, a0.w);
        a1.x = fmaf(w, v1.x, a1.x); a1.y = fmaf(w, v1.y, a1.y);
        a1.z = fmaf(w, v1.z, a1.z); a1.w = fmaf(w, v1.w, a1.w);
    }
    float dn = 1.f / (g_den[d * NH + hd] + 1e-16f);
    const float4 b0 = *(const float4*)&bias_gat[c0];
    const float4 b1 = *(const float4*)&bias_gat[c0 + 4];
    float4 o0, o1;
    o0.x = a0.x * dn + b0.x; o0.y = a0.y * dn + b0.y;
    o0.z = a0.z * dn + b0.z; o0.w = a0.w * dn + b0.w;
    o1.x = a1.x * dn + b1.x; o1.y = a1.y * dn + b1.y;
    o1.z = a1.z * dn + b1.z; o1.w = a1.w * dn + b1.w;
    o0.x = (o0.x > 0.f) ? o0.x : 0.01f * o0.x;  o0.y = (o0.y > 0.f) ? o0.y : 0.01f * o0.y;
    o0.z = (o0.z > 0.f) ? o0.z : 0.01f * o0.z;  o0.w = (o0.w > 0.f) ? o0.w : 0.01f * o0.w;
    o1.x = (o1.x > 0.f) ? o1.x : 0.01f * o1.x;  o1.y = (o1.y > 0.f) ? o1.y : 0.01f * o1.y;
    o1.z = (o1.z > 0.f) ? o1.z : 0.01f * o1.z;  o1.w = (o1.w > 0.f) ? o1.w : 0.01f * o1.w;
    float4* orow = (float4*)&g_gat[(size_t)d * OUTD + c0];
    orow[0] = o0; orow[1] = o1;
}

// ---------------- batch segment bounds --------------------------------------
__global__ void k_bstart(const int* __restrict__ batch)
{
    int t = threadIdx.x;
    if (t > NB) return;
    int lo = 0, hi = NN;
    while (lo < hi) { int mid = (lo + hi) >> 1; if (batch[mid] < t) lo = mid + 1; else hi = mid; }
    g_bstart[t] = lo;
}

// ---------------- pooling ----------------------------------------------------
__global__ __launch_bounds__(256) void k_pool()
{
    const int b = blockIdx.y;
    const int c4 = (blockIdx.x * 256 + threadIdx.x) * 4;
    const int beg = g_bstart[b], end = g_bstart[b + 1];
    float4 s = {0,0,0,0};
    float4 mx = {-INFINITY,-INFINITY,-INFINITY,-INFINITY};
    for (int n = beg; n < end; n++) {
        float4 v = *(const float4*)&g_gat[(size_t)n * OUTD + c4];
        s.x += v.x; s.y += v.y; s.z += v.z; s.w += v.w;
        mx.x = fmaxf(mx.x, v.x); mx.y = fmaxf(mx.y, v.y);
        mx.z = fmaxf(mx.z, v.z); mx.w = fmaxf(mx.w, v.w);
    }
    *(float4*)&g_pool[b * 4096 + c4]        = s;
    *(float4*)&g_pool[b * 4096 + 2048 + c4] = mx;
}

// ---------------- final MLPs -------------------------------------------------
__global__ __launch_bounds__(256)
void k_mlp(const float* __restrict__ W1r, const float* __restrict__ b1r,
           const float* __restrict__ W2r, const float* __restrict__ b2r,
           const float* __restrict__ W1m, const float* __restrict__ b1m,
           const float* __restrict__ W2m, const float* __restrict__ b2m,
           float* __restrict__ out)
{
    __shared__ float g[4096];
    __shared__ float hid[2][HIDD];
    const int b = blockIdx.x, t = threadIdx.x;
    const float inv = 1.f / fmaxf((float)(g_bstart[b + 1] - g_bstart[b]), 1.f);
    for (int i = t; i < 4096; i += 256) {
        float v = g_pool[b * 4096 + i];
        g[i] = (i < 2048) ? v * inv : v;
    }
    __syncthreads();
    const int warp = t >> 5, lane = t & 31;
    for (int p = warp; p < 64; p += 8) {
        int task = p >> 5, j = p & 31;
        const float* W1 = task ? W1m : W1r;
        const float* b1 = task ? b1m : b1r;
        float s = 0.f;
        for (int k = lane; k < 4096; k += 32) s = fmaf(g[k], W1[k * HIDD + j], s);
        #pragma unroll
        for (int o = 16; o > 0; o >>= 1) s += __shfl_down_sync(0xffffffff, s, o);
        if (lane == 0) hid[task][j] = fmaxf(s + b1[j], 0.f);
    }
    __syncthreads();
    if (t < 2) {
        const float* W2 = t ? W2m : W2r;
        float o = t ? b2m[0] : b2r[0];
        #pragma unroll
        for (int j = 0; j < HIDD; j++) o = fmaf(hid[t][j], W2[j], o);
        out[t * NB + b] = o;
    }
}

// ---------------- launch -----------------------------------------------------
extern "C" void kernel_launch(void* const* d_in, const int* in_sizes, int n_in,
                              void* d_out, int out_size)
{
    const int*   code  = (const int*)d_in[0];
    const int*   ei    = (const int*)d_in[1];
    const int*   batch = (const int*)d_in[2];
    const float* emb   = (const float*)d_in[3];
    const float* Wf    = (const float*)d_in[4];
    const float* bf    = (const float*)d_in[5];
    const float* Wg    = (const float*)d_in[6];
    const float* atts  = (const float*)d_in[7];
    const float* attd  = (const float*)d_in[8];
    const float* bg    = (const float*)d_in[9];
    const float* W1r   = (const float*)d_in[10];
    const float* b1r   = (const float*)d_in[11];
    const float* W2r   = (const float*)d_in[12];
    const float* b2r   = (const float*)d_in[13];
    const float* W1m   = (const float*)d_in[14];
    const float* b1m   = (const float*)d_in[15];
    const float* W2m   = (const float*)d_in[16];
    const float* b2m   = (const float*)d_in[17];
    float* out = (float*)d_out;

    const int* src = ei;
    const int* dst = ei + EE;

    cudaFuncSetAttribute(k_gemm<1>, cudaFuncAttributeMaxDynamicSharedMemorySize, GEMM_DYN);
    cudaFuncSetAttribute(k_gemm<2>, cudaFuncAttributeMaxDynamicSharedMemorySize, GEMM_DYN);

    __nv_bfloat16 *ah, *al, *xh, *xl, *wfh, *wfl, *wgh, *wgl;
    float *gh;
    cudaGetSymbolAddress((void**)&ah,  g_ah);
    cudaGetSymbolAddress((void**)&al,  g_al);
    cudaGetSymbolAddress((void**)&xh,  g_xh);
    cudaGetSymbolAddress((void**)&xl,  g_xl);
    cudaGetSymbolAddress((void**)&wfh, g_wfh);
    cudaGetSymbolAddress((void**)&wfl, g_wfl);
    cudaGetSymbolAddress((void**)&wgh, g_wgh);
    cudaGetSymbolAddress((void**)&wgl, g_wgl);
    cudaGetSymbolAddress((void**)&gh,  g_h);

    k_init<<<(NN * NH + 255) / 256, 256>>>();
    k_prep_emb<<<NN * 128 / 256, 256>>>(code, emb);
    k_prep_w<<<(EMBD * EMBD + 255) / 256, 256>>>(Wf, wfh, wfl, EMBD);
    k_prep_w<<<(OUTD * EMBD + 255) / 256, 256>>>(Wg, wgh, wgl, OUTD);

    // x = emb[code] @ W_feat + b_feat -> split bf16 (M=32768, N=512, K=512)
    k_gemm<1><<<dim3(EMBD / BN, NN / BM), 256, GEMM_DYN>>>(
        ah, al, wfh, wfl, bf, nullptr, nullptr, nullptr, xh, xl, EMBD);

    // h = x @ W_gat -> fp32 + fused attention dots (M=32768, N=2048, K=512)
    k_gemm<2><<<dim3(OUTD / BN, NN / BM), 256, GEMM_DYN>>>(
        xh, xl, wgh, wgl, nullptr, atts, attd, gh, nullptr, nullptr, OUTD);

    k_edge_logits<<<(ET + 255) / 256, 256>>>(src, dst);
    k_edge_exp<<<(ET + 255) / 256, 256>>>(src, dst);
    k_scan<<<1, 1024>>>();
    k_scatter<<<(ET + 255) / 256, 256>>>(dst);
    k_aggregate<<<NN, 256>>>(src, bg);
    k_bstart<<<1, 64>>>(batch);
    k_pool<<<dim3(OUTD / 1024, NB), 256>>>();
    k_mlp<<<NB, 256>>>(W1r, b1r, W2r, b2r, W1m, b1m, W2m, b2m, out);
}

// round 6
// speedup vs baseline: 1.8915x; 1.1287x over previous
#include <cuda_runtime.h>
#include <cuda_bf16.h>
#include <math.h>
#include <cstdint>

#define NN    32768
#define EMBD  512
#define NH    4
#define OUTD  2048
#define EE    131072
#define ET    (EE + NN)     // edges + self loops = 163840
#define NB    32
#define HIDD  32

// GEMM tiling: CTA 128x256, K-step 32, 8 warps (2 row x 4 col), warp tile 64x64
#define BM 128
#define BN 256
#define BK 32
#define KK 512
#define NSTEP (KK / BK)        // 16
// smem: 64B rows (32 bf16), XOR-swizzled 16B chunks: chunk' = chunk ^ ((row>>1)&3)
#define MATA_B (128 * 64)      // 8192 B per A matrix tile
#define MATB_B (256 * 64)      // 16384 B per B matrix tile
#define OFF_AH 0
#define OFF_AL MATA_B
#define OFF_BH (2 * MATA_B)
#define OFF_BL (2 * MATA_B + MATB_B)
#define STAGE_B (2 * MATA_B + 2 * MATB_B)   // 49152
#define GEMM_DYN (2 * STAGE_B)              // 98304

// ---------------- scratch (device globals; no allocation allowed) ----------
__device__ __nv_bfloat16 g_ah[(size_t)NN * EMBD];   // gathered emb, hi
__device__ __nv_bfloat16 g_al[(size_t)NN * EMBD];   // gathered emb, lo
__device__ __nv_bfloat16 g_xh[(size_t)NN * EMBD];   // x after feat linear, hi
__device__ __nv_bfloat16 g_xl[(size_t)NN * EMBD];
__device__ __nv_bfloat16 g_wfh[EMBD * EMBD];        // W_feat^T  [512,512] K-major
__device__ __nv_bfloat16 g_wfl[EMBD * EMBD];
__device__ __nv_bfloat16 g_wgh[(size_t)OUTD * EMBD];// W_gat^T   [2048,512] K-major
__device__ __nv_bfloat16 g_wgl[(size_t)OUTD * EMBD];
__device__ float    g_h  [(size_t)NN * OUTD];       // 256 MB
__device__ float    g_gat[(size_t)NN * OUTD];       // 256 MB
__device__ float    g_as [NN * NH];
__device__ float    g_ad [NN * NH];
__device__ unsigned g_amax[NN * NH];
__device__ float    g_den[NN * NH];
__device__ float    g_w  [ET * NH];
__device__ int      g_cnt[NN];
__device__ int      g_off[NN + 1];
__device__ int      g_cur[NN];
__device__ int      g_csr[ET];
__device__ int      g_bstart[NB + 1];
__device__ float    g_pool[NB * 2 * OUTD];

// ---------------- helpers ----------------------------------------------------
__device__ __forceinline__ uint32_t smem_u32(const void* p) {
    uint32_t a;
    asm("{ .reg .u64 t; cvta.to.shared.u64 t, %1; cvt.u32.u64 %0, t; }" : "=r"(a) : "l"(p));
    return a;
}
#define CP16(s, g) \
    asm volatile("cp.async.cg.shared.global [%0], [%1], 16;" :: "r"(s), "l"(g))
#define CP_COMMIT() asm volatile("cp.async.commit_group;" ::: "memory")
#define CP_WAIT1()  asm volatile("cp.async.wait_group 1;" ::: "memory")
#define CP_WAIT0()  asm volatile("cp.async.wait_group 0;" ::: "memory")
#define LDX4(r, a) \
    asm volatile("ldmatrix.sync.aligned.m8n8.x4.shared.b16 {%0,%1,%2,%3}, [%4];" \
        : "=r"((r)[0]), "=r"((r)[1]), "=r"((r)[2]), "=r"((r)[3]) : "r"(a))
#define MMA(d, a, b0, b1) \
    asm volatile("mma.sync.aligned.m16n8k16.row.col.f32.bf16.bf16.f32 " \
        "{%0,%1,%2,%3},{%4,%5,%6,%7},{%8,%9},{%0,%1,%2,%3};" \
        : "+f"((d)[0]), "+f"((d)[1]), "+f"((d)[2]), "+f"((d)[3]) \
        : "r"((a)[0]), "r"((a)[1]), "r"((a)[2]), "r"((a)[3]), "r"(b0), "r"(b1))

// swizzled smem byte offset for (row, 16B-chunk)
__device__ __forceinline__ uint32_t swz(int row, int chunk) {
    return (uint32_t)(row * 64 + ((chunk ^ (row >> 1)) & 3) * 16);
}

__device__ __forceinline__ void split2(float v, __nv_bfloat16& h, __nv_bfloat16& l) {
    h = __float2bfloat16(v);
    l = __float2bfloat16(v - __bfloat162float(h));
}
__device__ __forceinline__ unsigned encf(float f) {
    unsigned u = __float_as_uint(f);
    return (u & 0x80000000u) ? ~u : (u | 0x80000000u);
}
__device__ __forceinline__ float decf(unsigned u) {
    return __uint_as_float((u & 0x80000000u) ? (u ^ 0x80000000u) : ~u);
}
#define ENC_NEGINF 0x007FFFFFu

// ---------------- init ------------------------------------------------------
__global__ void k_init() {
    int i = blockIdx.x * blockDim.x + threadIdx.x;
    if (i < NN * NH) { g_amax[i] = ENC_NEGINF; g_den[i] = 0.f; g_as[i] = 0.f; g_ad[i] = 0.f; }
    if (i < NN)      { g_cnt[i] = 0; }
}

// ---------------- prep: gather emb rows + split to bf16 hi/lo ---------------
__global__ __launch_bounds__(256) void k_prep_emb(const int* __restrict__ code,
                                                  const float* __restrict__ emb)
{
    int id = blockIdx.x * 256 + threadIdx.x;        // NN*128 ids, 4 elems each
    int m = id >> 7, c4 = (id & 127) << 2;
    float4 v = *(const float4*)&emb[(size_t)code[m] * EMBD + c4];
    __nv_bfloat16 h[4], l[4];
    split2(v.x, h[0], l[0]); split2(v.y, h[1], l[1]);
    split2(v.z, h[2], l[2]); split2(v.w, h[3], l[3]);
    *(uint2*)&g_ah[(size_t)m * EMBD + c4] = *(uint2*)h;
    *(uint2*)&g_al[(size_t)m * EMBD + c4] = *(uint2*)l;
}

// ---------------- prep: W [K=512, Ncols] -> W^T hi/lo [Ncols, 512] ----------
__global__ __launch_bounds__(256) void k_prep_w(const float* __restrict__ W,
                                                __nv_bfloat16* __restrict__ Th,
                                                __nv_bfloat16* __restrict__ Tl, int Ncols)
{
    int id = blockIdx.x * 256 + threadIdx.x;
    if (id >= Ncols * EMBD) return;
    int n = id >> 9, k = id & 511;
    float v = W[(size_t)k * Ncols + n];
    __nv_bfloat16 h, l; split2(v, h, l);
    Th[(size_t)n * EMBD + k] = h;
    Tl[(size_t)n * EMBD + k] = l;
}

// ---------------- HMMA split-bf16 GEMM ---------------------------------------
// D[M,N] = (Ah+Al)[M,K] @ (Bh+Bl)^T  where B stored [N,K] K-major
// EPI==1: out = D + bias -> split bf16 (outH, outL)
// EPI==2: out = D fp32 -> outF, plus fused a_src/a_dst dot partials
template<int EPI>
__global__ __launch_bounds__(256, 1)
void k_gemm(const __nv_bfloat16* __restrict__ Ah, const __nv_bfloat16* __restrict__ Al,
            const __nv_bfloat16* __restrict__ Bh, const __nv_bfloat16* __restrict__ Bl,
            const float* __restrict__ bias,
            const float* __restrict__ atts, const float* __restrict__ attd,
            float* __restrict__ outF,
            __nv_bfloat16* __restrict__ outH, __nv_bfloat16* __restrict__ outL,
            int Nout)
{
    extern __shared__ __align__(128) char sm[];
    __shared__ float s_v1[BN], s_v2[BN], s_ps[BM], s_pd[BM];

    const int tid  = threadIdx.x;
    const int lane = tid & 31, wid = tid >> 5;
    const int wr = wid >> 2, wc = wid & 3;         // warp: 64-row block, 64-col block
    const int brow = blockIdx.y * BM;
    const int bcol = blockIdx.x * BN;

    if (EPI == 1) s_v1[tid] = bias[bcol + tid];
    else {
        s_v1[tid] = atts[bcol + tid];
        s_v2[tid] = attd[bcol + tid];
        if (tid < BM) { s_ps[tid] = 0.f; s_pd[tid] = 0.f; }
    }

    const uint32_t sbase = smem_u32(sm);

    auto load_stage = [&](int st, int k0) {
        const uint32_t so = sbase + st * STAGE_B;
        #pragma unroll
        for (int it = 0; it < 2; it++) {
            int i = tid + it * 256;                 // 512: rows 128 x 4 segs
            int row = i >> 2, seg = i & 3;
            uint32_t sofs = swz(row, seg);
            size_t ga = (size_t)(brow + row) * KK + k0 * BK + seg * 8;
            CP16(so + OFF_AH + sofs, Ah + ga);
            CP16(so + OFF_AL + sofs, Al + ga);
        }
        #pragma unroll
        for (int it = 0; it < 4; it++) {
            int i = tid + it * 256;                 // 1024: rows 256 x 4 segs
            int row = i >> 2, seg = i & 3;
            uint32_t sofs = swz(row, seg);
            size_t gb = (size_t)(bcol + row) * KK + k0 * BK + seg * 8;
            CP16(so + OFF_BH + sofs, Bh + gb);
            CP16(so + OFF_BL + sofs, Bl + gb);
        }
    };

    float d[4][8][4];
    #pragma unroll
    for (int mt = 0; mt < 4; mt++)
        #pragma unroll
        for (int nt = 0; nt < 8; nt++)
            #pragma unroll
            for (int j = 0; j < 4; j++) d[mt][nt][j] = 0.f;

    // lane-fixed fragment coordinates
    const int arow = wr * 64 + (lane & 15);
    const int akh  = lane >> 4;                            // A k-half chunk
    const int brow_l = wc * 64 + ((lane >> 4) & 1) * 8 + (lane & 7);
    const int bkh  = (lane >> 3) & 1;                      // B k-half chunk

    load_stage(0, 0);
    CP_COMMIT();

    for (int k0 = 0; k0 < NSTEP; k0++) {
        const int st = k0 & 1;
        if (k0 + 1 < NSTEP) { load_stage(st ^ 1, k0 + 1); CP_COMMIT(); CP_WAIT1(); }
        else                { CP_WAIT0(); }
        __syncthreads();

        const uint32_t so = sbase + st * STAGE_B;

        #pragma unroll
        for (int ks = 0; ks < 2; ks++) {
            uint32_t ah[4][4], bh[4][4], xl[4][4];
            #pragma unroll
            for (int mt = 0; mt < 4; mt++) {
                int r = arow + mt * 16;
                LDX4(ah[mt], so + OFF_AH + swz(r, ks * 2 + akh));
            }
            #pragma unroll
            for (int np = 0; np < 4; np++) {
                int r = brow_l + np * 16;
                LDX4(bh[np], so + OFF_BH + swz(r, ks * 2 + bkh));
            }
            #pragma unroll
            for (int mt = 0; mt < 4; mt++)
                #pragma unroll
                for (int nt = 0; nt < 8; nt++)
                    MMA(d[mt][nt], ah[mt], bh[nt >> 1][(nt & 1) * 2], bh[nt >> 1][(nt & 1) * 2 + 1]);
            // Al * Bh
            #pragma unroll
            for (int mt = 0; mt < 4; mt++) {
                int r = arow + mt * 16;
                LDX4(xl[mt], so + OFF_AL + swz(r, ks * 2 + akh));
            }
            #pragma unroll
            for (int mt = 0; mt < 4; mt++)
                #pragma unroll
                for (int nt = 0; nt < 8; nt++)
                    MMA(d[mt][nt], xl[mt], bh[nt >> 1][(nt & 1) * 2], bh[nt >> 1][(nt & 1) * 2 + 1]);
            // Ah * Bl
            #pragma unroll
            for (int np = 0; np < 4; np++) {
                int r = brow_l + np * 16;
                LDX4(xl[np], so + OFF_BL + swz(r, ks * 2 + bkh));
            }
            #pragma unroll
            for (int mt = 0; mt < 4; mt++)
                #pragma unroll
                for (int nt = 0; nt < 8; nt++)
                    MMA(d[mt][nt], ah[mt], xl[nt >> 1][(nt & 1) * 2], xl[nt >> 1][(nt & 1) * 2 + 1]);
        }
        __syncthreads();
    }

    // ---------------- epilogue ----------------
    const int gid = lane >> 2, tig = lane & 3;
    float ps0[4] = {0,0,0,0}, ps1[4] = {0,0,0,0};
    float pd0[4] = {0,0,0,0}, pd1[4] = {0,0,0,0};

    #pragma unroll
    for (int mt = 0; mt < 4; mt++) {
        const int r0 = wr * 64 + mt * 16 + gid;
        #pragma unroll
        for (int nt = 0; nt < 8; nt++) {
            const int c = wc * 64 + nt * 8 + tig * 2;
            float v0 = d[mt][nt][0], v1 = d[mt][nt][1];
            float v2 = d[mt][nt][2], v3 = d[mt][nt][3];
            if (EPI == 1) {
                __nv_bfloat16 h0, l0, h1, l1;
                split2(v0 + s_v1[c], h0, l0); split2(v1 + s_v1[c + 1], h1, l1);
                __nv_bfloat162 hp; hp.x = h0; hp.y = h1;
                __nv_bfloat162 lp; lp.x = l0; lp.y = l1;
                *(__nv_bfloat162*)(outH + (size_t)(brow + r0) * Nout + bcol + c) = hp;
                *(__nv_bfloat162*)(outL + (size_t)(brow + r0) * Nout + bcol + c) = lp;
                split2(v2 + s_v1[c], h0, l0); split2(v3 + s_v1[c + 1], h1, l1);
                hp.x = h0; hp.y = h1; lp.x = l0; lp.y = l1;
                *(__nv_bfloat162*)(outH + (size_t)(brow + r0 + 8) * Nout + bcol + c) = hp;
                *(__nv_bfloat162*)(outL + (size_t)(brow + r0 + 8) * Nout + bcol + c) = lp;
            } else {
                float2 f01 = make_float2(v0, v1);
                float2 f23 = make_float2(v2, v3);
                *(float2*)(outF + (size_t)(brow + r0) * Nout + bcol + c) = f01;
                *(float2*)(outF + (size_t)(brow + r0 + 8) * Nout + bcol + c) = f23;
                float w0 = s_v1[c], w1 = s_v1[c + 1];
                float u0 = s_v2[c], u1 = s_v2[c + 1];
                ps0[mt] = fmaf(v0, w0, fmaf(v1, w1, ps0[mt]));
                ps1[mt] = fmaf(v2, w0, fmaf(v3, w1, ps1[mt]));
                pd0[mt] = fmaf(v0, u0, fmaf(v1, u1, pd0[mt]));
                pd1[mt] = fmaf(v2, u0, fmaf(v3, u1, pd1[mt]));
            }
        }
    }
    if (EPI == 2) {
        __syncthreads();
        #pragma unroll
        for (int mt = 0; mt < 4; mt++) {
            const int r0 = wr * 64 + mt * 16 + gid;
            atomicAdd(&s_ps[r0], ps0[mt]);     atomicAdd(&s_ps[r0 + 8], ps1[mt]);
            atomicAdd(&s_pd[r0], pd0[mt]);     atomicAdd(&s_pd[r0 + 8], pd1[mt]);
        }
        __syncthreads();
        if (tid < BM) {
            const int head = bcol >> 9;        // 256-col tile lies inside one 512-col head
            atomicAdd(&g_as[(brow + tid) * NH + head], s_ps[tid]);
            atomicAdd(&g_ad[(brow + tid) * NH + head], s_pd[tid]);
        }
    }
}

// ---------------- edge logits + segment max + degree counts -----------------
__global__ void k_edge_logits(const int* __restrict__ src, const int* __restrict__ dst)
{
    int e = blockIdx.x * blockDim.x + threadIdx.x;
    if (e >= ET) return;
    int s = (e < EE) ? src[e] : (e - EE);
    int d = (e < EE) ? dst[e] : (e - EE);
    #pragma unroll
    for (int h = 0; h < NH; h++) {
        float v = g_as[s * NH + h] + g_ad[d * NH + h];
        v = (v > 0.f) ? v : 0.2f * v;
        g_w[e * NH + h] = v;
        atomicMax(&g_amax[d * NH + h], encf(v));
    }
    atomicAdd(&g_cnt[d], 1);
}

__global__ void k_edge_exp(const int* __restrict__ src, const int* __restrict__ dst)
{
    int e = blockIdx.x * blockDim.x + threadIdx.x;
    if (e >= ET) return;
    int d = (e < EE) ? dst[e] : (e - EE);
    #pragma unroll
    for (int h = 0; h < NH; h++) {
        float m = decf(g_amax[d * NH + h]);
        float w = __expf(g_w[e * NH + h] - m);
        g_w[e * NH + h] = w;
        atomicAdd(&g_den[d * NH + h], w);
    }
}

// ---------------- exclusive scan of counts ----------------------------------
__global__ __launch_bounds__(1024) void k_scan()
{
    __shared__ int sm[1024];
    const int t = threadIdx.x, base = t * 32;
    int s = 0;
    for (int i = 0; i < 32; i++) s += g_cnt[base + i];
    sm[t] = s;
    __syncthreads();
    for (int o = 1; o < 1024; o <<= 1) {
        int v = (t >= o) ? sm[t - o] : 0;
        __syncthreads();
        sm[t] += v;
        __syncthreads();
    }
    int run = sm[t] - s;
    for (int i = 0; i < 32; i++) {
        g_off[base + i] = run;
        g_cur[base + i] = run;
        run += g_cnt[base + i];
    }
    if (t == 1023) g_off[NN] = sm[1023];
}

__global__ void k_scatter(const int* __restrict__ dst)
{
    int e = blockIdx.x * blockDim.x + threadIdx.x;
    if (e >= ET) return;
    int d = (e < EE) ? dst[e] : (e - EE);
    int pos = atomicAdd(&g_cur[d], 1);
    g_csr[pos] = e;
}

// ---------------- aggregation ------------------------------------------------
__global__ __launch_bounds__(256)
void k_aggregate(const int* __restrict__ src, const float* __restrict__ bias_gat)
{
    const int d = blockIdx.x, t = threadIdx.x;
    const int c0 = t * 8;
    const int hd = t >> 6;
    float4 a0 = {0,0,0,0}, a1 = {0,0,0,0};
    const int beg = g_off[d], end = g_off[d + 1];
    for (int p = beg; p < end; p++) {
        int e = g_csr[p];
        int s = (e < EE) ? src[e] : (e - EE);
        float w = g_w[e * NH + hd];
        const float4* hr = (const float4*)&g_h[(size_t)s * OUTD + c0];
        float4 v0 = hr[0], v1 = hr[1];
        a0.x = fmaf(w, v0.x, a0.x); a0.y = fmaf(w, v0.y, a0.y);
        a0.z = fmaf(w, v0.z, a0.z); a0.w = fmaf(w, v0.w, a0.w);
        a1.x = fmaf(w, v1.x, a1.x); a1.y = fmaf(w, v1.y, a1.y);
        a1.z = fmaf(w, v1.z, a1.z); a1.w = fmaf(w, v1.w, a1.w);
    }
    float dn = 1.f / (g_den[d * NH + hd] + 1e-16f);
    const float4 b0 = *(const float4*)&bias_gat[c0];
    const float4 b1 = *(const float4*)&bias_gat[c0 + 4];
    float4 o0, o1;
    o0.x = a0.x * dn + b0.x; o0.y = a0.y * dn + b0.y;
    o0.z = a0.z * dn + b0.z; o0.w = a0.w * dn + b0.w;
    o1.x = a1.x * dn + b1.x; o1.y = a1.y * dn + b1.y;
    o1.z = a1.z * dn + b1.z; o1.w = a1.w * dn + b1.w;
    o0.x = (o0.x > 0.f) ? o0.x : 0.01f * o0.x;  o0.y = (o0.y > 0.f) ? o0.y : 0.01f * o0.y;
    o0.z = (o0.z > 0.f) ? o0.z : 0.01f * o0.z;  o0.w = (o0.w > 0.f) ? o0.w : 0.01f * o0.w;
    o1.x = (o1.x > 0.f) ? o1.x : 0.01f * o1.x;  o1.y = (o1.y > 0.f) ? o1.y : 0.01f * o1.y;
    o1.z = (o1.z > 0.f) ? o1.z : 0.01f * o1.z;  o1.w = (o1.w > 0.f) ? o1.w : 0.01f * o1.w;
    float4* orow = (float4*)&g_gat[(size_t)d * OUTD + c0];
    orow[0] = o0; orow[1] = o1;
}

// ---------------- batch segment bounds --------------------------------------
__global__ void k_bstart(const int* __restrict__ batch)
{
    int t = threadIdx.x;
    if (t > NB) return;
    int lo = 0, hi = NN;
    while (lo < hi) { int mid = (lo + hi) >> 1; if (batch[mid] < t) lo = mid + 1; else hi = mid; }
    g_bstart[t] = lo;
}

// ---------------- pooling ----------------------------------------------------
__global__ __launch_bounds__(256) void k_pool()
{
    const int b = blockIdx.y;
    const int c4 = (blockIdx.x * 256 + threadIdx.x) * 4;
    const int beg = g_bstart[b], end = g_bstart[b + 1];
    float4 s = {0,0,0,0};
    float4 mx = {-INFINITY,-INFINITY,-INFINITY,-INFINITY};
    for (int n = beg; n < end; n++) {
        float4 v = *(const float4*)&g_gat[(size_t)n * OUTD + c4];
        s.x += v.x; s.y += v.y; s.z += v.z; s.w += v.w;
        mx.x = fmaxf(mx.x, v.x); mx.y = fmaxf(mx.y, v.y);
        mx.z = fmaxf(mx.z, v.z); mx.w = fmaxf(mx.w, v.w);
    }
    *(float4*)&g_pool[b * 4096 + c4]        = s;
    *(float4*)&g_pool[b * 4096 + 2048 + c4] = mx;
}

// ---------------- final MLPs -------------------------------------------------
__global__ __launch_bounds__(256)
void k_mlp(const float* __restrict__ W1r, const float* __restrict__ b1r,
           const float* __restrict__ W2r, const float* __restrict__ b2r,
           const float* __restrict__ W1m, const float* __restrict__ b1m,
           const float* __restrict__ W2m, const float* __restrict__ b2m,
           float* __restrict__ out)
{
    __shared__ float g[4096];
    __shared__ float hid[2][HIDD];
    const int b = blockIdx.x, t = threadIdx.x;
    const float inv = 1.f / fmaxf((float)(g_bstart[b + 1] - g_bstart[b]), 1.f);
    for (int i = t; i < 4096; i += 256) {
        float v = g_pool[b * 4096 + i];
        g[i] = (i < 2048) ? v * inv : v;
    }
    __syncthreads();
    const int warp = t >> 5, lane = t & 31;
    for (int p = warp; p < 64; p += 8) {
        int task = p >> 5, j = p & 31;
        const float* W1 = task ? W1m : W1r;
        const float* b1 = task ? b1m : b1r;
        float s = 0.f;
        for (int k = lane; k < 4096; k += 32) s = fmaf(g[k], W1[k * HIDD + j], s);
        #pragma unroll
        for (int o = 16; o > 0; o >>= 1) s += __shfl_down_sync(0xffffffff, s, o);
        if (lane == 0) hid[task][j] = fmaxf(s + b1[j], 0.f);
    }
    __syncthreads();
    if (t < 2) {
        const float* W2 = t ? W2m : W2r;
        float o = t ? b2m[0] : b2r[0];
        #pragma unroll
        for (int j = 0; j < HIDD; j++) o = fmaf(hid[t][j], W2[j], o);
        out[t * NB + b] = o;
    }
}

// ---------------- launch -----------------------------------------------------
extern "C" void kernel_launch(void* const* d_in, const int* in_sizes, int n_in,
                              void* d_out, int out_size)
{
    const int*   code  = (const int*)d_in[0];
    const int*   ei    = (const int*)d_in[1];
    const int*   batch = (const int*)d_in[2];
    const float* emb   = (const float*)d_in[3];
    const float* Wf    = (const float*)d_in[4];
    const float* bf    = (const float*)d_in[5];
    const float* Wg    = (const float*)d_in[6];
    const float* atts  = (const float*)d_in[7];
    const float* attd  = (const float*)d_in[8];
    const float* bg    = (const float*)d_in[9];
    const float* W1r   = (const float*)d_in[10];
    const float* b1r   = (const float*)d_in[11];
    const float* W2r   = (const float*)d_in[12];
    const float* b2r   = (const float*)d_in[13];
    const float* W1m   = (const float*)d_in[14];
    const float* b1m   = (const float*)d_in[15];
    const float* W2m   = (const float*)d_in[16];
    const float* b2m   = (const float*)d_in[17];
    float* out = (float*)d_out;

    const int* src = ei;
    const int* dst = ei + EE;

    cudaFuncSetAttribute(k_gemm<1>, cudaFuncAttributeMaxDynamicSharedMemorySize, GEMM_DYN);
    cudaFuncSetAttribute(k_gemm<2>, cudaFuncAttributeMaxDynamicSharedMemorySize, GEMM_DYN);

    __nv_bfloat16 *ah, *al, *xh, *xl, *wfh, *wfl, *wgh, *wgl;
    float *gh;
    cudaGetSymbolAddress((void**)&ah,  g_ah);
    cudaGetSymbolAddress((void**)&al,  g_al);
    cudaGetSymbolAddress((void**)&xh,  g_xh);
    cudaGetSymbolAddress((void**)&xl,  g_xl);
    cudaGetSymbolAddress((void**)&wfh, g_wfh);
    cudaGetSymbolAddress((void**)&wfl, g_wfl);
    cudaGetSymbolAddress((void**)&wgh, g_wgh);
    cudaGetSymbolAddress((void**)&wgl, g_wgl);
    cudaGetSymbolAddress((void**)&gh,  g_h);

    k_init<<<(NN * NH + 255) / 256, 256>>>();
    k_prep_emb<<<NN * 128 / 256, 256>>>(code, emb);
    k_prep_w<<<(EMBD * EMBD + 255) / 256, 256>>>(Wf, wfh, wfl, EMBD);
    k_prep_w<<<(OUTD * EMBD + 255) / 256, 256>>>(Wg, wgh, wgl, OUTD);

    // x = emb[code] @ W_feat + b_feat -> split bf16 (M=32768, N=512, K=512)
    k_gemm<1><<<dim3(EMBD / BN, NN / BM), 256, GEMM_DYN>>>(
        ah, al, wfh, wfl, bf, nullptr, nullptr, nullptr, xh, xl, EMBD);

    // h = x @ W_gat -> fp32 + fused attention dots (M=32768, N=2048, K=512)
    k_gemm<2><<<dim3(OUTD / BN, NN / BM), 256, GEMM_DYN>>>(
        xh, xl, wgh, wgl, nullptr, atts, attd, gh, nullptr, nullptr, OUTD);

    k_edge_logits<<<(ET + 255) / 256, 256>>>(src, dst);
    k_edge_exp<<<(ET + 255) / 256, 256>>>(src, dst);
    k_scan<<<1, 1024>>>();
    k_scatter<<<(ET + 255) / 256, 256>>>(dst);
    k_aggregate<<<NN, 256>>>(src, bg);
    k_bstart<<<1, 64>>>(batch);
    k_pool<<<dim3(OUTD / 1024, NB), 256>>>();
    k_mlp<<<NB, 256>>>(W1r, b1r, W2r, b2r, W1m, b1m, W2m, b2m, out);
}

// round 9
// speedup vs baseline: 2.2144x; 1.1707x over previous
#include <cuda_runtime.h>
#include <cuda_bf16.h>
#include <math.h>
#include <cstdint>

#define NN    32768
#define EMBD  512
#define NH    4
#define OUTD  2048
#define EE    131072
#define ET    (EE + NN)     // edges + self loops = 163840
#define NB    32
#define HIDD  32

// GEMM tiling: CTA 128x256, K-step 32, 8 warps (2 row x 4 col), warp tile 64x64
#define BM 128
#define BN 256
#define BK 32
#define KK 512
#define NSTEP (KK / BK)        // 16
// smem: 64B rows (32 bf16), XOR-swizzled 16B chunks: chunk' = chunk ^ ((row>>1)&3)
#define MATA_B (128 * 64)      // 8192 B per A matrix tile
#define MATB_B (256 * 64)      // 16384 B per B matrix tile
#define OFF_AH 0
#define OFF_AL MATA_B
#define OFF_BH (2 * MATA_B)
#define OFF_BL (2 * MATA_B + MATB_B)
#define STAGE_B (2 * MATA_B + 2 * MATB_B)   // 49152
#define GEMM_DYN (3 * STAGE_B)              // 147456 (3-stage)

// ---------------- scratch (device globals; no allocation allowed) ----------
__device__ __nv_bfloat16 g_ah[(size_t)NN * EMBD];   // gathered emb, hi
__device__ __nv_bfloat16 g_al[(size_t)NN * EMBD];   // gathered emb, lo
__device__ __nv_bfloat16 g_xh[(size_t)NN * EMBD];   // x after feat linear, hi
__device__ __nv_bfloat16 g_xl[(size_t)NN * EMBD];
__device__ __nv_bfloat16 g_wfh[EMBD * EMBD];        // W_feat^T  [512,512] K-major
__device__ __nv_bfloat16 g_wfl[EMBD * EMBD];
__device__ __nv_bfloat16 g_wgh[(size_t)OUTD * EMBD];// W_gat^T   [2048,512] K-major
__device__ __nv_bfloat16 g_wgl[(size_t)OUTD * EMBD];
__device__ float    g_h  [(size_t)NN * OUTD];       // 256 MB (MUST stay fp32: final
                                                    // outputs cancel; bf16 h -> 1.6e-3)
__device__ float    g_gat[(size_t)NN * OUTD];       // 256 MB
__device__ float    g_as [NN * NH];
__device__ float    g_ad [NN * NH];
__device__ unsigned g_amax[NN * NH];
__device__ float    g_den[NN * NH];
__device__ float    g_w  [ET * NH];
__device__ int      g_cnt[NN];
__device__ int      g_off[NN + 1];
__device__ int      g_cur[NN];
__device__ int      g_csr[ET];
__device__ int      g_bstart[NB + 1];
__device__ float    g_pool[NB * OUTD];              // mean-pool sums (atomic)
__device__ unsigned g_pmax[NB * OUTD];              // max-pool, ordered-uint (atomic)

// ---------------- helpers ----------------------------------------------------
__device__ __forceinline__ uint32_t smem_u32(const void* p) {
    uint32_t a;
    asm("{ .reg .u64 t; cvta.to.shared.u64 t, %1; cvt.u32.u64 %0, t; }" : "=r"(a) : "l"(p));
    return a;
}
#define CP16(s, g) \
    asm volatile("cp.async.cg.shared.global [%0], [%1], 16;" :: "r"(s), "l"(g))
#define CP_COMMIT() asm volatile("cp.async.commit_group;" ::: "memory")
#define CP_WAIT2()  asm volatile("cp.async.wait_group 2;" ::: "memory")
#define CP_WAIT1()  asm volatile("cp.async.wait_group 1;" ::: "memory")
#define CP_WAIT0()  asm volatile("cp.async.wait_group 0;" ::: "memory")
#define LDX4(r, a) \
    asm volatile("ldmatrix.sync.aligned.m8n8.x4.shared.b16 {%0,%1,%2,%3}, [%4];" \
        : "=r"((r)[0]), "=r"((r)[1]), "=r"((r)[2]), "=r"((r)[3]) : "r"(a))
#define MMA(d, a, b0, b1) \
    asm volatile("mma.sync.aligned.m16n8k16.row.col.f32.bf16.bf16.f32 " \
        "{%0,%1,%2,%3},{%4,%5,%6,%7},{%8,%9},{%0,%1,%2,%3};" \
        : "+f"((d)[0]), "+f"((d)[1]), "+f"((d)[2]), "+f"((d)[3]) \
        : "r"((a)[0]), "r"((a)[1]), "r"((a)[2]), "r"((a)[3]), "r"(b0), "r"(b1))

// swizzled smem byte offset for (row, 16B-chunk)
__device__ __forceinline__ uint32_t swz(int row, int chunk) {
    return (uint32_t)(row * 64 + ((chunk ^ (row >> 1)) & 3) * 16);
}

__device__ __forceinline__ void split2(float v, __nv_bfloat16& h, __nv_bfloat16& l) {
    h = __float2bfloat16(v);
    l = __float2bfloat16(v - __bfloat162float(h));
}
__device__ __forceinline__ unsigned encf(float f) {
    unsigned u = __float_as_uint(f);
    return (u & 0x80000000u) ? ~u : (u | 0x80000000u);
}
__device__ __forceinline__ float decf(unsigned u) {
    return __uint_as_float((u & 0x80000000u) ? (u ^ 0x80000000u) : ~u);
}
#define ENC_NEGINF 0x007FFFFFu

// ---------------- init ------------------------------------------------------
__global__ void k_init() {
    int i = blockIdx.x * blockDim.x + threadIdx.x;
    if (i < NN * NH) { g_amax[i] = ENC_NEGINF; g_den[i] = 0.f; g_as[i] = 0.f; g_ad[i] = 0.f; }
    if (i < NN)      { g_cnt[i] = 0; }
    if (i < NB * OUTD) { g_pool[i] = 0.f; g_pmax[i] = ENC_NEGINF; }
}

// ---------------- prep: gather emb rows + split to bf16 hi/lo ---------------
__global__ __launch_bounds__(256) void k_prep_emb(const int* __restrict__ code,
                                                  const float* __restrict__ emb)
{
    int id = blockIdx.x * 256 + threadIdx.x;        // NN*128 ids, 4 elems each
    int m = id >> 7, c4 = (id & 127) << 2;
    float4 v = *(const float4*)&emb[(size_t)code[m] * EMBD + c4];
    __nv_bfloat16 h[4], l[4];
    split2(v.x, h[0], l[0]); split2(v.y, h[1], l[1]);
    split2(v.z, h[2], l[2]); split2(v.w, h[3], l[3]);
    *(uint2*)&g_ah[(size_t)m * EMBD + c4] = *(uint2*)h;
    *(uint2*)&g_al[(size_t)m * EMBD + c4] = *(uint2*)l;
}

// ---------------- prep: W [K=512, Ncols] -> W^T hi/lo [Ncols, 512] ----------
__global__ __launch_bounds__(256) void k_prep_w(const float* __restrict__ W,
                                                __nv_bfloat16* __restrict__ Th,
                                                __nv_bfloat16* __restrict__ Tl, int Ncols)
{
    int id = blockIdx.x * 256 + threadIdx.x;
    if (id >= Ncols * EMBD) return;
    int n = id >> 9, k = id & 511;
    float v = W[(size_t)k * Ncols + n];
    __nv_bfloat16 h, l; split2(v, h, l);
    Th[(size_t)n * EMBD + k] = h;
    Tl[(size_t)n * EMBD + k] = l;
}

// ---------------- HMMA split-bf16 GEMM (3-stage cp.async) --------------------
// D[M,N] = (Ah+Al)[M,K] @ (Bh+Bl)^T  where B stored [N,K] K-major
// EPI==1: out = D + bias -> split bf16 (outH, outL)
// EPI==2: out = D fp32 -> outF, plus fused a_src/a_dst dot partials (fp32 exact)
template<int EPI>
__global__ __launch_bounds__(256, 1)
void k_gemm(const __nv_bfloat16* __restrict__ Ah, const __nv_bfloat16* __restrict__ Al,
            const __nv_bfloat16* __restrict__ Bh, const __nv_bfloat16* __restrict__ Bl,
            const float* __restrict__ bias,
            const float* __restrict__ atts, const float* __restrict__ attd,
            float* __restrict__ outF,
            __nv_bfloat16* __restrict__ outH, __nv_bfloat16* __restrict__ outL,
            int Nout)
{
    extern __shared__ __align__(128) char sm[];
    __shared__ float s_v1[BN], s_v2[BN], s_ps[BM], s_pd[BM];

    const int tid  = threadIdx.x;
    const int lane = tid & 31, wid = tid >> 5;
    const int wr = wid >> 2, wc = wid & 3;         // warp: 64-row block, 64-col block
    const int brow = blockIdx.y * BM;
    const int bcol = blockIdx.x * BN;

    if (EPI == 1) s_v1[tid] = bias[bcol + tid];
    else {
        s_v1[tid] = atts[bcol + tid];
        s_v2[tid] = attd[bcol + tid];
        if (tid < BM) { s_ps[tid] = 0.f; s_pd[tid] = 0.f; }
    }

    const uint32_t sbase = smem_u32(sm);

    auto load_stage = [&](int st, int k0) {
        const uint32_t so = sbase + st * STAGE_B;
        #pragma unroll
        for (int it = 0; it < 2; it++) {
            int i = tid + it * 256;                 // 512: rows 128 x 4 segs
            int row = i >> 2, seg = i & 3;
            uint32_t sofs = swz(row, seg);
            size_t ga = (size_t)(brow + row) * KK + k0 * BK + seg * 8;
            CP16(so + OFF_AH + sofs, Ah + ga);
            CP16(so + OFF_AL + sofs, Al + ga);
        }
        #pragma unroll
        for (int it = 0; it < 4; it++) {
            int i = tid + it * 256;                 // 1024: rows 256 x 4 segs
            int row = i >> 2, seg = i & 3;
            uint32_t sofs = swz(row, seg);
            size_t gb = (size_t)(bcol + row) * KK + k0 * BK + seg * 8;
            CP16(so + OFF_BH + sofs, Bh + gb);
            CP16(so + OFF_BL + sofs, Bl + gb);
        }
    };

    float d[4][8][4];
    #pragma unroll
    for (int mt = 0; mt < 4; mt++)
        #pragma unroll
        for (int nt = 0; nt < 8; nt++)
            #pragma unroll
            for (int j = 0; j < 4; j++) d[mt][nt][j] = 0.f;

    // lane-fixed fragment coordinates
    const int arow = wr * 64 + (lane & 15);
    const int akh  = lane >> 4;                            // A k-half chunk
    const int brow_l = wc * 64 + ((lane >> 4) & 1) * 8 + (lane & 7);
    const int bkh  = (lane >> 3) & 1;                      // B k-half chunk

    load_stage(0, 0); CP_COMMIT();
    load_stage(1, 1); CP_COMMIT();

    int st = 0;
    for (int k0 = 0; k0 < NSTEP; k0++) {
        if (k0 + 2 < NSTEP) {
            int s2 = st + 2; if (s2 >= 3) s2 -= 3;
            load_stage(s2, k0 + 2); CP_COMMIT(); CP_WAIT2();
        } else if (k0 + 1 < NSTEP) CP_WAIT1();
        else CP_WAIT0();
        __syncthreads();

        const uint32_t so = sbase + st * STAGE_B;

        #pragma unroll
        for (int ks = 0; ks < 2; ks++) {
            uint32_t ah[4][4], bh[4][4], xl[4][4];
            #pragma unroll
            for (int mt = 0; mt < 4; mt++) {
                int r = arow + mt * 16;
                LDX4(ah[mt], so + OFF_AH + swz(r, ks * 2 + akh));
            }
            #pragma unroll
            for (int np = 0; np < 4; np++) {
                int r = brow_l + np * 16;
                LDX4(bh[np], so + OFF_BH + swz(r, ks * 2 + bkh));
            }
            #pragma unroll
            for (int mt = 0; mt < 4; mt++)
                #pragma unroll
                for (int nt = 0; nt < 8; nt++)
                    MMA(d[mt][nt], ah[mt], bh[nt >> 1][(nt & 1) * 2], bh[nt >> 1][(nt & 1) * 2 + 1]);
            // Al * Bh
            #pragma unroll
            for (int mt = 0; mt < 4; mt++) {
                int r = arow + mt * 16;
                LDX4(xl[mt], so + OFF_AL + swz(r, ks * 2 + akh));
            }
            #pragma unroll
            for (int mt = 0; mt < 4; mt++)
                #pragma unroll
                for (int nt = 0; nt < 8; nt++)
                    MMA(d[mt][nt], xl[mt], bh[nt >> 1][(nt & 1) * 2], bh[nt >> 1][(nt & 1) * 2 + 1]);
            // Ah * Bl
            #pragma unroll
            for (int np = 0; np < 4; np++) {
                int r = brow_l + np * 16;
                LDX4(xl[np], so + OFF_BL + swz(r, ks * 2 + bkh));
            }
            #pragma unroll
            for (int mt = 0; mt < 4; mt++)
                #pragma unroll
                for (int nt = 0; nt < 8; nt++)
                    MMA(d[mt][nt], ah[mt], xl[nt >> 1][(nt & 1) * 2], xl[nt >> 1][(nt & 1) * 2 + 1]);
        }
        __syncthreads();
        if (++st == 3) st = 0;
    }

    // ---------------- epilogue ----------------
    const int gid = lane >> 2, tig = lane & 3;
    float ps0[4] = {0,0,0,0}, ps1[4] = {0,0,0,0};
    float pd0[4] = {0,0,0,0}, pd1[4] = {0,0,0,0};

    #pragma unroll
    for (int mt = 0; mt < 4; mt++) {
        const int r0 = wr * 64 + mt * 16 + gid;
        #pragma unroll
        for (int nt = 0; nt < 8; nt++) {
            const int c = wc * 64 + nt * 8 + tig * 2;
            float v0 = d[mt][nt][0], v1 = d[mt][nt][1];
            float v2 = d[mt][nt][2], v3 = d[mt][nt][3];
            if (EPI == 1) {
                __nv_bfloat16 h0, l0, h1, l1;
                split2(v0 + s_v1[c], h0, l0); split2(v1 + s_v1[c + 1], h1, l1);
                __nv_bfloat162 hp; hp.x = h0; hp.y = h1;
                __nv_bfloat162 lp; lp.x = l0; lp.y = l1;
                *(__nv_bfloat162*)(outH + (size_t)(brow + r0) * Nout + bcol + c) = hp;
                *(__nv_bfloat162*)(outL + (size_t)(brow + r0) * Nout + bcol + c) = lp;
                split2(v2 + s_v1[c], h0, l0); split2(v3 + s_v1[c + 1], h1, l1);
                hp.x = h0; hp.y = h1; lp.x = l0; lp.y = l1;
                *(__nv_bfloat162*)(outH + (size_t)(brow + r0 + 8) * Nout + bcol + c) = hp;
                *(__nv_bfloat162*)(outL + (size_t)(brow + r0 + 8) * Nout + bcol + c) = lp;
            } else {
                float2 f01 = make_float2(v0, v1);
                float2 f23 = make_float2(v2, v3);
                *(float2*)(outF + (size_t)(brow + r0) * Nout + bcol + c) = f01;
                *(float2*)(outF + (size_t)(brow + r0 + 8) * Nout + bcol + c) = f23;
                float w0 = s_v1[c], w1 = s_v1[c + 1];
                float u0 = s_v2[c], u1 = s_v2[c + 1];
                ps0[mt] = fmaf(v0, w0, fmaf(v1, w1, ps0[mt]));
                ps1[mt] = fmaf(v2, w0, fmaf(v3, w1, ps1[mt]));
                pd0[mt] = fmaf(v0, u0, fmaf(v1, u1, pd0[mt]));
                pd1[mt] = fmaf(v2, u0, fmaf(v3, u1, pd1[mt]));
            }
        }
    }
    if (EPI == 2) {
        __syncthreads();
        #pragma unroll
        for (int mt = 0; mt < 4; mt++) {
            const int r0 = wr * 64 + mt * 16 + gid;
            atomicAdd(&s_ps[r0], ps0[mt]);     atomicAdd(&s_ps[r0 + 8], ps1[mt]);
            atomicAdd(&s_pd[r0], pd0[mt]);     atomicAdd(&s_pd[r0 + 8], pd1[mt]);
        }
        __syncthreads();
        if (tid < BM) {
            const int head = bcol >> 9;        // 256-col tile lies inside one 512-col head
            atomicAdd(&g_as[(brow + tid) * NH + head], s_ps[tid]);
            atomicAdd(&g_ad[(brow + tid) * NH + head], s_pd[tid]);
        }
    }
}

// ---------------- edge logits + segment max + degree counts -----------------
__global__ void k_edge_logits(const int* __restrict__ src, const int* __restrict__ dst)
{
    int e = blockIdx.x * blockDim.x + threadIdx.x;
    if (e >= ET) return;
    int s = (e < EE) ? src[e] : (e - EE);
    int d = (e < EE) ? dst[e] : (e - EE);
    #pragma unroll
    for (int h = 0; h < NH; h++) {
        float v = g_as[s * NH + h] + g_ad[d * NH + h];
        v = (v > 0.f) ? v : 0.2f * v;
        g_w[e * NH + h] = v;
        atomicMax(&g_amax[d * NH + h], encf(v));
    }
    atomicAdd(&g_cnt[d], 1);
}

// ---------------- fused: edge exp + denom + CSR scatter ----------------------
__global__ void k_edge_exp_scatter(const int* __restrict__ src, const int* __restrict__ dst)
{
    int e = blockIdx.x * blockDim.x + threadIdx.x;
    if (e >= ET) return;
    int d = (e < EE) ? dst[e] : (e - EE);
    #pragma unroll
    for (int h = 0; h < NH; h++) {
        float m = decf(g_amax[d * NH + h]);
        float w = __expf(g_w[e * NH + h] - m);
        g_w[e * NH + h] = w;
        atomicAdd(&g_den[d * NH + h], w);
    }
    int pos = atomicAdd(&g_cur[d], 1);
    g_csr[pos] = e;
}

// ---------------- exclusive scan of counts ----------------------------------
__global__ __launch_bounds__(1024) void k_scan()
{
    __shared__ int sm[1024];
    const int t = threadIdx.x, base = t * 32;
    int s = 0;
    for (int i = 0; i < 32; i++) s += g_cnt[base + i];
    sm[t] = s;
    __syncthreads();
    for (int o = 1; o < 1024; o <<= 1) {
        int v = (t >= o) ? sm[t - o] : 0;
        __syncthreads();
        sm[t] += v;
        __syncthreads();
    }
    int run = sm[t] - s;
    for (int i = 0; i < 32; i++) {
        g_off[base + i] = run;
        g_cur[base + i] = run;
        run += g_cnt[base + i];
    }
    if (t == 1023) g_off[NN] = sm[1023];
}

// ---------------- aggregation (fp32 h gather) --------------------------------
__global__ __launch_bounds__(256)
void k_aggregate(const int* __restrict__ src, const float* __restrict__ bias_gat)
{
    const int d = blockIdx.x, t = threadIdx.x;
    const int c0 = t * 8;
    const int hd = t >> 6;
    float4 a0 = {0,0,0,0}, a1 = {0,0,0,0};
    const int beg = g_off[d], end = g_off[d + 1];
    for (int p = beg; p < end; p++) {
        int e = g_csr[p];
        int s = (e < EE) ? src[e] : (e - EE);
        float w = g_w[e * NH + hd];
        const float4* hr = (const float4*)&g_h[(size_t)s * OUTD + c0];
        float4 v0 = hr[0], v1 = hr[1];
        a0.x = fmaf(w, v0.x, a0.x); a0.y = fmaf(w, v0.y, a0.y);
        a0.z = fmaf(w, v0.z, a0.z); a0.w = fmaf(w, v0.w, a0.w);
        a1.x = fmaf(w, v1.x, a1.x); a1.y = fmaf(w, v1.y, a1.y);
        a1.z = fmaf(w, v1.z, a1.z); a1.w = fmaf(w, v1.w, a1.w);
    }
    float dn = 1.f / (g_den[d * NH + hd] + 1e-16f);
    const float4 b0 = *(const float4*)&bias_gat[c0];
    const float4 b1 = *(const float4*)&bias_gat[c0 + 4];
    float4 o0, o1;
    o0.x = a0.x * dn + b0.x; o0.y = a0.y * dn + b0.y;
    o0.z = a0.z * dn + b0.z; o0.w = a0.w * dn + b0.w;
    o1.x = a1.x * dn + b1.x; o1.y = a1.y * dn + b1.y;
    o1.z = a1.z * dn + b1.z; o1.w = a1.w * dn + b1.w;
    o0.x = (o0.x > 0.f) ? o0.x : 0.01f * o0.x;  o0.y = (o0.y > 0.f) ? o0.y : 0.01f * o0.y;
    o0.z = (o0.z > 0.f) ? o0.z : 0.01f * o0.z;  o0.w = (o0.w > 0.f) ? o0.w : 0.01f * o0.w;
    o1.x = (o1.x > 0.f) ? o1.x : 0.01f * o1.x;  o1.y = (o1.y > 0.f) ? o1.y : 0.01f * o1.y;
    o1.z = (o1.z > 0.f) ? o1.z : 0.01f * o1.z;  o1.w = (o1.w > 0.f) ? o1.w : 0.01f * o1.w;
    float4* orow = (float4*)&g_gat[(size_t)d * OUTD + c0];
    orow[0] = o0; orow[1] = o1;
}

// ---------------- batch segment bounds --------------------------------------
__global__ void k_bstart(const int* __restrict__ batch)
{
    int t = threadIdx.x;
    if (t > NB) return;
    int lo = 0, hi = NN;
    while (lo < hi) { int mid = (lo + hi) >> 1; if (batch[mid] < t) lo = mid + 1; else hi = mid; }
    g_bstart[t] = lo;
}

// ---------------- pooling (parallel: 8 node chunks per graph, atomics) -------
__global__ __launch_bounds__(256) void k_pool()
{
    const int b = blockIdx.y;
    const int chunk = blockIdx.z;
    const int c4 = (blockIdx.x * 256 + threadIdx.x) * 4;
    const int beg0 = g_bstart[b], len = g_bstart[b + 1] - beg0;
    const int beg = beg0 + (int)(((long long)len * chunk) >> 3);
    const int end = beg0 + (int)(((long long)len * (chunk + 1)) >> 3);
    float4 s = {0,0,0,0};
    float4 mx = {-INFINITY,-INFINITY,-INFINITY,-INFINITY};
    for (int n = beg; n < end; n++) {
        float4 v = *(const float4*)&g_gat[(size_t)n * OUTD + c4];
        s.x += v.x; s.y += v.y; s.z += v.z; s.w += v.w;
        mx.x = fmaxf(mx.x, v.x); mx.y = fmaxf(mx.y, v.y);
        mx.z = fmaxf(mx.z, v.z); mx.w = fmaxf(mx.w, v.w);
    }
    if (beg < end) {
        float* sp = &g_pool[b * OUTD + c4];
        unsigned* mp = &g_pmax[b * OUTD + c4];
        atomicAdd(sp + 0, s.x); atomicAdd(sp + 1, s.y);
        atomicAdd(sp + 2, s.z); atomicAdd(sp + 3, s.w);
        atomicMax(mp + 0, encf(mx.x)); atomicMax(mp + 1, encf(mx.y));
        atomicMax(mp + 2, encf(mx.z)); atomicMax(mp + 3, encf(mx.w));
    }
}

// ---------------- final MLPs -------------------------------------------------
__global__ __launch_bounds__(256)
void k_mlp(const float* __restrict__ W1r, const float* __restrict__ b1r,
           const float* __restrict__ W2r, const float* __restrict__ b2r,
           const float* __restrict__ W1m, const float* __restrict__ b1m,
           const float* __restrict__ W2m, const float* __restrict__ b2m,
           float* __restrict__ out)
{
    __shared__ float g[4096];
    __shared__ float hid[2][HIDD];
    const int b = blockIdx.x, t = threadIdx.x;
    const float inv = 1.f / fmaxf((float)(g_bstart[b + 1] - g_bstart[b]), 1.f);
    for (int i = t; i < 4096; i += 256) {
        float v;
        if (i < 2048) v = g_pool[b * OUTD + i] * inv;
        else          v = decf(g_pmax[b * OUTD + i - 2048]);
        g[i] = v;
    }
    __syncthreads();
    const int warp = t >> 5, lane = t & 31;
    for (int p = warp; p < 64; p += 8) {
        int task = p >> 5, j = p & 31;
        const float* W1 = task ? W1m : W1r;
        const float* b1 = task ? b1m : b1r;
        float s = 0.f;
        for (int k = lane; k < 4096; k += 32) s = fmaf(g[k], W1[k * HIDD + j], s);
        #pragma unroll
        for (int o = 16; o > 0; o >>= 1) s += __shfl_down_sync(0xffffffff, s, o);
        if (lane == 0) hid[task][j] = fmaxf(s + b1[j], 0.f);
    }
    __syncthreads();
    if (t < 2) {
        const float* W2 = t ? W2m : W2r;
        float o = t ? b2m[0] : b2r[0];
        #pragma unroll
        for (int j = 0; j < HIDD; j++) o = fmaf(hid[t][j], W2[j], o);
        out[t * NB + b] = o;
    }
}

// ---------------- launch -----------------------------------------------------
extern "C" void kernel_launch(void* const* d_in, const int* in_sizes, int n_in,
                              void* d_out, int out_size)
{
    const int*   code  = (const int*)d_in[0];
    const int*   ei    = (const int*)d_in[1];
    const int*   batch = (const int*)d_in[2];
    const float* emb   = (const float*)d_in[3];
    const float* Wf    = (const float*)d_in[4];
    const float* bf    = (const float*)d_in[5];
    const float* Wg    = (const float*)d_in[6];
    const float* atts  = (const float*)d_in[7];
    const float* attd  = (const float*)d_in[8];
    const float* bg    = (const float*)d_in[9];
    const float* W1r   = (const float*)d_in[10];
    const float* b1r   = (const float*)d_in[11];
    const float* W2r   = (const float*)d_in[12];
    const float* b2r   = (const float*)d_in[13];
    const float* W1m   = (const float*)d_in[14];
    const float* b1m   = (const float*)d_in[15];
    const float* W2m   = (const float*)d_in[16];
    const float* b2m   = (const float*)d_in[17];
    float* out = (float*)d_out;

    const int* src = ei;
    const int* dst = ei + EE;

    cudaFuncSetAttribute(k_gemm<1>, cudaFuncAttributeMaxDynamicSharedMemorySize, GEMM_DYN);
    cudaFuncSetAttribute(k_gemm<2>, cudaFuncAttributeMaxDynamicSharedMemorySize, GEMM_DYN);

    __nv_bfloat16 *ah, *al, *xh, *xl, *wfh, *wfl, *wgh, *wgl;
    float *gh;
    cudaGetSymbolAddress((void**)&ah,  g_ah);
    cudaGetSymbolAddress((void**)&al,  g_al);
    cudaGetSymbolAddress((void**)&xh,  g_xh);
    cudaGetSymbolAddress((void**)&xl,  g_xl);
    cudaGetSymbolAddress((void**)&wfh, g_wfh);
    cudaGetSymbolAddress((void**)&wfl, g_wfl);
    cudaGetSymbolAddress((void**)&wgh, g_wgh);
    cudaGetSymbolAddress((void**)&wgl, g_wgl);
    cudaGetSymbolAddress((void**)&gh,  g_h);

    k_init<<<(NN * NH + 255) / 256, 256>>>();
    k_prep_emb<<<NN * 128 / 256, 256>>>(code, emb);
    k_prep_w<<<(EMBD * EMBD + 255) / 256, 256>>>(Wf, wfh, wfl, EMBD);
    k_prep_w<<<(OUTD * EMBD + 255) / 256, 256>>>(Wg, wgh, wgl, OUTD);

    // x = emb[code] @ W_feat + b_feat -> split bf16 (M=32768, N=512, K=512)
    k_gemm<1><<<dim3(EMBD / BN, NN / BM), 256, GEMM_DYN>>>(
        ah, al, wfh, wfl, bf, nullptr, nullptr, nullptr, xh, xl, EMBD);

    // h = x @ W_gat -> fp32 + fused attention dots (M=32768, N=2048, K=512)
    k_gemm<2><<<dim3(OUTD / BN, NN / BM), 256, GEMM_DYN>>>(
        xh, xl, wgh, wgl, nullptr, atts, attd, gh, nullptr, nullptr, OUTD);

    k_edge_logits<<<(ET + 255) / 256, 256>>>(src, dst);
    k_scan<<<1, 1024>>>();
    k_edge_exp_scatter<<<(ET + 255) / 256, 256>>>(src, dst);
    k_aggregate<<<NN, 256>>>(src, bg);
    k_bstart<<<1, 64>>>(batch);
    k_pool<<<dim3(OUTD / 1024, NB, 8), 256>>>();
    k_mlp<<<NB, 256>>>(W1r, b1r, W2r, b2r, W1m, b1m, W2m, b2m, out);
}

// round 12
// speedup vs baseline: 2.6178x; 1.1822x over previous
#include <cuda_runtime.h>
#include <cuda_bf16.h>
#include <math.h>
#include <cstdint>

#define NN    32768
#define EMBD  512
#define NH    4
#define OUTD  2048
#define EE    131072
#define ET    (EE + NN)     // edges + self loops = 163840
#define NB    32
#define HIDD  32

// GEMM tiling: CTA 128x256, K-step 32, 8 warps (2 row x 4 col), warp tile 64x64
#define BM 128
#define BN 256
#define BK 32
#define KK 512
#define NSTEP (KK / BK)        // 16
// smem: 64B rows (32 bf16), XOR-swizzled 16B chunks: chunk' = chunk ^ ((row>>1)&3)
#define MATA_B (128 * 64)      // 8192 B per A matrix tile
#define MATB_B (256 * 64)      // 16384 B per B matrix tile
#define OFF_AH 0
#define OFF_AL MATA_B
#define OFF_BH (2 * MATA_B)
#define OFF_BL (2 * MATA_B + MATB_B)
#define STAGE_B (2 * MATA_B + 2 * MATB_B)   // 49152
#define GEMM_DYN (3 * STAGE_B)              // 147456 (3-stage)

// ---------------- scratch (device globals; no allocation allowed) ----------
__device__ __nv_bfloat16 g_ah[(size_t)NN * EMBD];   // gathered emb, hi
__device__ __nv_bfloat16 g_al[(size_t)NN * EMBD];   // gathered emb, lo
__device__ __nv_bfloat16 g_xh[(size_t)NN * EMBD];   // x after feat linear, hi
__device__ __nv_bfloat16 g_xl[(size_t)NN * EMBD];
__device__ __nv_bfloat16 g_wfh[EMBD * EMBD];        // W_feat^T  [512,512] K-major
__device__ __nv_bfloat16 g_wfl[EMBD * EMBD];
__device__ __nv_bfloat16 g_wgh[(size_t)OUTD * EMBD];// W_gat^T   [2048,512] K-major
__device__ __nv_bfloat16 g_wgl[(size_t)OUTD * EMBD];
__device__ __nv_bfloat16 g_yh[(size_t)NH * NN * EMBD]; // aggregated x per head, hi
__device__ __nv_bfloat16 g_yl[(size_t)NH * NN * EMBD]; // lo
__device__ float    g_ws[NH * EMBD];                // W_gat_head @ att_src_head
__device__ float    g_wd[NH * EMBD];
__device__ float    g_as [NN * NH];
__device__ float    g_ad [NN * NH];
__device__ unsigned g_amax[NN * NH];
__device__ float    g_den[NN * NH];
__device__ float    g_w  [ET * NH];
__device__ int      g_cnt[NN];
__device__ int      g_off[NN + 1];
__device__ int      g_cur[NN];
__device__ int      g_csr[ET];
__device__ int      g_bstart[NB + 1];
__device__ float    g_pool[NB * OUTD];              // mean-pool sums (atomic)
__device__ unsigned g_pmax[NB * OUTD];              // max-pool, ordered-uint (atomic)

// ---------------- helpers ----------------------------------------------------
__device__ __forceinline__ uint32_t smem_u32(const void* p) {
    uint32_t a;
    asm("{ .reg .u64 t; cvta.to.shared.u64 t, %1; cvt.u32.u64 %0, t; }" : "=r"(a) : "l"(p));
    return a;
}
#define CP16(s, g) \
    asm volatile("cp.async.cg.shared.global [%0], [%1], 16;" :: "r"(s), "l"(g))
#define CP_COMMIT() asm volatile("cp.async.commit_group;" ::: "memory")
#define CP_WAIT2()  asm volatile("cp.async.wait_group 2;" ::: "memory")
#define CP_WAIT1()  asm volatile("cp.async.wait_group 1;" ::: "memory")
#define CP_WAIT0()  asm volatile("cp.async.wait_group 0;" ::: "memory")
#define LDX4(r, a) \
    asm volatile("ldmatrix.sync.aligned.m8n8.x4.shared.b16 {%0,%1,%2,%3}, [%4];" \
        : "=r"((r)[0]), "=r"((r)[1]), "=r"((r)[2]), "=r"((r)[3]) : "r"(a))
#define MMA(d, a, b0, b1) \
    asm volatile("mma.sync.aligned.m16n8k16.row.col.f32.bf16.bf16.f32 " \
        "{%0,%1,%2,%3},{%4,%5,%6,%7},{%8,%9},{%0,%1,%2,%3};" \
        : "+f"((d)[0]), "+f"((d)[1]), "+f"((d)[2]), "+f"((d)[3]) \
        : "r"((a)[0]), "r"((a)[1]), "r"((a)[2]), "r"((a)[3]), "r"(b0), "r"(b1))

// swizzled smem byte offset for (row, 16B-chunk)
__device__ __forceinline__ uint32_t swz(int row, int chunk) {
    return (uint32_t)(row * 64 + ((chunk ^ (row >> 1)) & 3) * 16);
}

__device__ __forceinline__ void split2(float v, __nv_bfloat16& h, __nv_bfloat16& l) {
    h = __float2bfloat16(v);
    l = __float2bfloat16(v - __bfloat162float(h));
}
__device__ __forceinline__ unsigned encf(float f) {
    unsigned u = __float_as_uint(f);
    return (u & 0x80000000u) ? ~u : (u | 0x80000000u);
}
__device__ __forceinline__ float decf(unsigned u) {
    return __uint_as_float((u & 0x80000000u) ? (u ^ 0x80000000u) : ~u);
}
#define ENC_NEGINF 0x007FFFFFu

// ---------------- init ------------------------------------------------------
__global__ void k_init() {
    int i = blockIdx.x * blockDim.x + threadIdx.x;
    if (i < NN * NH) { g_amax[i] = ENC_NEGINF; g_den[i] = 0.f; g_as[i] = 0.f; g_ad[i] = 0.f; }
    if (i < NN)      { g_cnt[i] = 0; }
    if (i < NB * OUTD) { g_pool[i] = 0.f; g_pmax[i] = ENC_NEGINF; }
}

// ---------------- prep: gather emb rows + split to bf16 hi/lo ---------------
__global__ __launch_bounds__(256) void k_prep_emb(const int* __restrict__ code,
                                                  const float* __restrict__ emb)
{
    int id = blockIdx.x * 256 + threadIdx.x;        // NN*128 ids, 4 elems each
    int m = id >> 7, c4 = (id & 127) << 2;
    float4 v = *(const float4*)&emb[(size_t)code[m] * EMBD + c4];
    __nv_bfloat16 h[4], l[4];
    split2(v.x, h[0], l[0]); split2(v.y, h[1], l[1]);
    split2(v.z, h[2], l[2]); split2(v.w, h[3], l[3]);
    *(uint2*)&g_ah[(size_t)m * EMBD + c4] = *(uint2*)h;
    *(uint2*)&g_al[(size_t)m * EMBD + c4] = *(uint2*)l;
}

// ---------------- prep: W [K=512, Ncols] -> W^T hi/lo [Ncols, 512] ----------
__global__ __launch_bounds__(256) void k_prep_w(const float* __restrict__ W,
                                                __nv_bfloat16* __restrict__ Th,
                                                __nv_bfloat16* __restrict__ Tl, int Ncols)
{
    int id = blockIdx.x * 256 + threadIdx.x;
    if (id >= Ncols * EMBD) return;
    int n = id >> 9, k = id & 511;
    float v = W[(size_t)k * Ncols + n];
    __nv_bfloat16 h, l; split2(v, h, l);
    Th[(size_t)n * EMBD + k] = h;
    Tl[(size_t)n * EMBD + k] = l;
}

// ---------------- prep: w~s[h][k] = sum_c Wg[k, h*512+c]*atts[h,c] ----------
// 2048 outputs total (NH*EMBD); one warp per output.
__global__ __launch_bounds__(256) void k_prep_att(const float* __restrict__ Wg,
                                                  const float* __restrict__ atts,
                                                  const float* __restrict__ attd)
{
    int wid = threadIdx.x >> 5, lane = threadIdx.x & 31;
    int o = blockIdx.x * 8 + wid;          // 2048 outputs
    if (o >= NH * EMBD) return;
    int h = o >> 9, k = o & 511;
    const float* row = Wg + (size_t)k * OUTD + h * EMBD;
    const float* va  = atts + h * EMBD;
    const float* vd  = attd + h * EMBD;
    float ss = 0.f, sd = 0.f;
    #pragma unroll
    for (int c = lane; c < EMBD; c += 32) {
        float w = row[c];
        ss = fmaf(w, va[c], ss);
        sd = fmaf(w, vd[c], sd);
    }
    #pragma unroll
    for (int off = 16; off > 0; off >>= 1) {
        ss += __shfl_down_sync(0xffffffffu, ss, off);
        sd += __shfl_down_sync(0xffffffffu, sd, off);
    }
    if (lane == 0) { g_ws[o] = ss; g_wd[o] = sd; }
}

// ---------------- HMMA split-bf16 GEMM (3-stage cp.async) --------------------
// D[M,N] = (Ah+Al)[M,K] @ (Bh+Bl)^T  where B stored [N,K] K-major
// EPI==1: x-GEMM: out = D + bias -> split bf16 (outH,outL); fused a_src/a_dst
//         dots via g_ws/g_wd (fp32 exact, atomics to g_as/g_ad)
// EPI==3: per-head y-GEMM (blockIdx.z = head): v = leaky(D + bias_gat);
//         fused mean/max pooling into g_pool/g_pmax (nothing else written)
template<int EPI>
__global__ __launch_bounds__(256, 1)
void k_gemm(const __nv_bfloat16* __restrict__ Ah, const __nv_bfloat16* __restrict__ Al,
            const __nv_bfloat16* __restrict__ Bh, const __nv_bfloat16* __restrict__ Bl,
            const float* __restrict__ bias, const int* __restrict__ batch,
            __nv_bfloat16* __restrict__ outH, __nv_bfloat16* __restrict__ outL)
{
    extern __shared__ __align__(128) char sm[];
    __shared__ float s_bias[BN];
    __shared__ float s_ws[4 * BN], s_wd[4 * BN];      // EPI1
    __shared__ float s_as[BM * 4], s_ad[BM * 4];      // EPI1
    __shared__ float s_cs[2 * BN], s_cm[2 * BN];      // EPI3
    __shared__ int   s_batch[BM];                     // EPI3

    const int tid  = threadIdx.x;
    const int lane = tid & 31, wid = tid >> 5;
    const int wr = wid >> 2, wc = wid & 3;         // warp: 64-row block, 64-col block
    const int brow = blockIdx.y * BM;
    const int bcol = blockIdx.x * BN;
    const int head = (EPI == 3) ? blockIdx.z : 0;

    if (EPI == 1) {
        s_bias[tid] = bias[bcol + tid];
        #pragma unroll
        for (int h = 0; h < 4; h++) {
            s_ws[h * BN + tid] = g_ws[h * EMBD + bcol + tid];
            s_wd[h * BN + tid] = g_wd[h * EMBD + bcol + tid];
        }
        #pragma unroll
        for (int i = tid; i < BM * 4; i += 256) { s_as[i] = 0.f; s_ad[i] = 0.f; }
    } else {
        s_bias[tid] = bias[head * 512 + bcol + tid];
    }

    const __nv_bfloat16* Ah_ = Ah + (EPI == 3 ? (size_t)head * NN * KK : 0);
    const __nv_bfloat16* Al_ = Al + (EPI == 3 ? (size_t)head * NN * KK : 0);
    const int bofs = (EPI == 3) ? head * 512 : 0;

    const uint32_t sbase = smem_u32(sm);

    auto load_stage = [&](int st, int k0) {
        const uint32_t so = sbase + st * STAGE_B;
        #pragma unroll
        for (int it = 0; it < 2; it++) {
            int i = tid + it * 256;                 // 512: rows 128 x 4 segs
            int row = i >> 2, seg = i & 3;
            uint32_t sofs = swz(row, seg);
            size_t ga = (size_t)(brow + row) * KK + k0 * BK + seg * 8;
            CP16(so + OFF_AH + sofs, Ah_ + ga);
            CP16(so + OFF_AL + sofs, Al_ + ga);
        }
        #pragma unroll
        for (int it = 0; it < 4; it++) {
            int i = tid + it * 256;                 // 1024: rows 256 x 4 segs
            int row = i >> 2, seg = i & 3;
            uint32_t sofs = swz(row, seg);
            size_t gb = (size_t)(bofs + bcol + row) * KK + k0 * BK + seg * 8;
            CP16(so + OFF_BH + sofs, Bh + gb);
            CP16(so + OFF_BL + sofs, Bl + gb);
        }
    };

    float d[4][8][4];
    #pragma unroll
    for (int mt = 0; mt < 4; mt++)
        #pragma unroll
        for (int nt = 0; nt < 8; nt++)
            #pragma unroll
            for (int j = 0; j < 4; j++) d[mt][nt][j] = 0.f;

    // lane-fixed fragment coordinates
    const int arow = wr * 64 + (lane & 15);
    const int akh  = lane >> 4;                            // A k-half chunk
    const int brow_l = wc * 64 + ((lane >> 4) & 1) * 8 + (lane & 7);
    const int bkh  = (lane >> 3) & 1;                      // B k-half chunk

    load_stage(0, 0); CP_COMMIT();
    load_stage(1, 1); CP_COMMIT();

    int st = 0;
    for (int k0 = 0; k0 < NSTEP; k0++) {
        if (k0 + 2 < NSTEP) {
            int s2 = st + 2; if (s2 >= 3) s2 -= 3;
            load_stage(s2, k0 + 2); CP_COMMIT(); CP_WAIT2();
        } else if (k0 + 1 < NSTEP) CP_WAIT1();
        else CP_WAIT0();
        __syncthreads();

        const uint32_t so = sbase + st * STAGE_B;

        #pragma unroll
        for (int ks = 0; ks < 2; ks++) {
            uint32_t ah[4][4], bh[4][4], xl[4][4];
            #pragma unroll
            for (int mt = 0; mt < 4; mt++) {
                int r = arow + mt * 16;
                LDX4(ah[mt], so + OFF_AH + swz(r, ks * 2 + akh));
            }
            #pragma unroll
            for (int np = 0; np < 4; np++) {
                int r = brow_l + np * 16;
                LDX4(bh[np], so + OFF_BH + swz(r, ks * 2 + bkh));
            }
            #pragma unroll
            for (int mt = 0; mt < 4; mt++)
                #pragma unroll
                for (int nt = 0; nt < 8; nt++)
                    MMA(d[mt][nt], ah[mt], bh[nt >> 1][(nt & 1) * 2], bh[nt >> 1][(nt & 1) * 2 + 1]);
            // Al * Bh
            #pragma unroll
            for (int mt = 0; mt < 4; mt++) {
                int r = arow + mt * 16;
                LDX4(xl[mt], so + OFF_AL + swz(r, ks * 2 + akh));
            }
            #pragma unroll
            for (int mt = 0; mt < 4; mt++)
                #pragma unroll
                for (int nt = 0; nt < 8; nt++)
                    MMA(d[mt][nt], xl[mt], bh[nt >> 1][(nt & 1) * 2], bh[nt >> 1][(nt & 1) * 2 + 1]);
            // Ah * Bl
            #pragma unroll
            for (int np = 0; np < 4; np++) {
                int r = brow_l + np * 16;
                LDX4(xl[np], so + OFF_BL + swz(r, ks * 2 + bkh));
            }
            #pragma unroll
            for (int mt = 0; mt < 4; mt++)
                #pragma unroll
                for (int nt = 0; nt < 8; nt++)
                    MMA(d[mt][nt], ah[mt], xl[nt >> 1][(nt & 1) * 2], xl[nt >> 1][(nt & 1) * 2 + 1]);
        }
        __syncthreads();
        if (++st == 3) st = 0;
    }

    // ---------------- epilogue ----------------
    const int gid = lane >> 2, tig = lane & 3;

    if (EPI == 1) {
        #pragma unroll
        for (int mt = 0; mt < 4; mt++) {
            const int r0 = wr * 64 + mt * 16 + gid;
            float as0[4] = {0,0,0,0}, as1[4] = {0,0,0,0};
            float ad0[4] = {0,0,0,0}, ad1[4] = {0,0,0,0};
            #pragma unroll
            for (int nt = 0; nt < 8; nt++) {
                const int c = wc * 64 + nt * 8 + tig * 2;
                float v0 = d[mt][nt][0] + s_bias[c];
                float v1 = d[mt][nt][1] + s_bias[c + 1];
                float v2 = d[mt][nt][2] + s_bias[c];
                float v3 = d[mt][nt][3] + s_bias[c + 1];
                __nv_bfloat16 h0, l0, h1, l1;
                split2(v0, h0, l0); split2(v1, h1, l1);
                __nv_bfloat162 hp; hp.x = h0; hp.y = h1;
                __nv_bfloat162 lp; lp.x = l0; lp.y = l1;
                *(__nv_bfloat162*)(outH + (size_t)(brow + r0) * EMBD + bcol + c) = hp;
                *(__nv_bfloat162*)(outL + (size_t)(brow + r0) * EMBD + bcol + c) = lp;
                split2(v2, h0, l0); split2(v3, h1, l1);
                hp.x = h0; hp.y = h1; lp.x = l0; lp.y = l1;
                *(__nv_bfloat162*)(outH + (size_t)(brow + r0 + 8) * EMBD + bcol + c) = hp;
                *(__nv_bfloat162*)(outL + (size_t)(brow + r0 + 8) * EMBD + bcol + c) = lp;
                #pragma unroll
                for (int h = 0; h < 4; h++) {
                    float w0 = s_ws[h * BN + c], w1 = s_ws[h * BN + c + 1];
                    float u0 = s_wd[h * BN + c], u1 = s_wd[h * BN + c + 1];
                    as0[h] = fmaf(v0, w0, fmaf(v1, w1, as0[h]));
                    as1[h] = fmaf(v2, w0, fmaf(v3, w1, as1[h]));
                    ad0[h] = fmaf(v0, u0, fmaf(v1, u1, ad0[h]));
                    ad1[h] = fmaf(v2, u0, fmaf(v3, u1, ad1[h]));
                }
            }
            #pragma unroll
            for (int h = 0; h < 4; h++) {
                #pragma unroll
                for (int o = 1; o <= 2; o <<= 1) {
                    as0[h] += __shfl_xor_sync(0xffffffffu, as0[h], o);
                    as1[h] += __shfl_xor_sync(0xffffffffu, as1[h], o);
                    ad0[h] += __shfl_xor_sync(0xffffffffu, ad0[h], o);
                    ad1[h] += __shfl_xor_sync(0xffffffffu, ad1[h], o);
                }
            }
            if (tig == 0) {
                #pragma unroll
                for (int h = 0; h < 4; h++) {
                    atomicAdd(&s_as[r0 * 4 + h], as0[h]);
                    atomicAdd(&s_as[(r0 + 8) * 4 + h], as1[h]);
                    atomicAdd(&s_ad[r0 * 4 + h], ad0[h]);
                    atomicAdd(&s_ad[(r0 + 8) * 4 + h], ad1[h]);
                }
            }
        }
        __syncthreads();
        if (tid < BM) {
            #pragma unroll
            for (int h = 0; h < 4; h++) {
                atomicAdd(&g_as[(brow + tid) * NH + h], s_as[tid * 4 + h]);
                atomicAdd(&g_ad[(brow + tid) * NH + h], s_ad[tid * 4 + h]);
            }
        }
    } else {
        // v = leaky(D + bias) in place
        #pragma unroll
        for (int mt = 0; mt < 4; mt++)
            #pragma unroll
            for (int nt = 0; nt < 8; nt++) {
                const int c = wc * 64 + nt * 8 + tig * 2;
                float v;
                v = d[mt][nt][0] + s_bias[c];     d[mt][nt][0] = (v > 0.f) ? v : 0.01f * v;
                v = d[mt][nt][1] + s_bias[c + 1]; d[mt][nt][1] = (v > 0.f) ? v : 0.01f * v;
                v = d[mt][nt][2] + s_bias[c];     d[mt][nt][2] = (v > 0.f) ? v : 0.01f * v;
                v = d[mt][nt][3] + s_bias[c + 1]; d[mt][nt][3] = (v > 0.f) ? v : 0.01f * v;
            }
        if (tid < BM) s_batch[tid] = batch[brow + tid];
        __syncthreads();
        const int gA = s_batch[0], gB = s_batch[BM - 1];
        const int npass = (gA == gB) ? 1 : 2;     // 128-row tile spans <=2 graphs
        for (int pass = 0; pass < npass; pass++) {
            const int gsel = pass ? gB : gA;
            bool msk[4][2];
            #pragma unroll
            for (int mt = 0; mt < 4; mt++)
                #pragma unroll
                for (int hf = 0; hf < 2; hf++)
                    msk[mt][hf] = (s_batch[wr * 64 + mt * 16 + gid + hf * 8] == gsel);
            #pragma unroll
            for (int nt = 0; nt < 8; nt++) {
                #pragma unroll
                for (int j2 = 0; j2 < 2; j2++) {
                    float sv = 0.f, mv = -INFINITY;
                    #pragma unroll
                    for (int mt = 0; mt < 4; mt++)
                        #pragma unroll
                        for (int hf = 0; hf < 2; hf++) {
                            float v = d[mt][nt][hf * 2 + j2];
                            if (msk[mt][hf]) { sv += v; mv = fmaxf(mv, v); }
                        }
                    #pragma unroll
                    for (int o = 4; o <= 16; o <<= 1) {
                        sv += __shfl_xor_sync(0xffffffffu, sv, o);
                        mv = fmaxf(mv, __shfl_xor_sync(0xffffffffu, mv, o));
                    }
                    if (gid == 0) {
                        int cl = wc * 64 + nt * 8 + tig * 2 + j2;
                        s_cs[wr * BN + cl] = sv;
                        s_cm[wr * BN + cl] = mv;
                    }
                }
            }
            __syncthreads();
            {
                float sv = s_cs[tid] + s_cs[BN + tid];
                float mv = fmaxf(s_cm[tid], s_cm[BN + tid]);
                int colg = head * 512 + bcol + tid;
                atomicAdd(&g_pool[gsel * OUTD + colg], sv);
                atomicMax(&g_pmax[gsel * OUTD + colg], encf(mv));
            }
            __syncthreads();
        }
    }
}

// ---------------- edge logits + segment max + degree counts -----------------
__global__ void k_edge_logits(const int* __restrict__ src, const int* __restrict__ dst)
{
    int e = blockIdx.x * blockDim.x + threadIdx.x;
    if (e >= ET) return;
    int s = (e < EE) ? src[e] : (e - EE);
    int d = (e < EE) ? dst[e] : (e - EE);
    #pragma unroll
    for (int h = 0; h < NH; h++) {
        float v = g_as[s * NH + h] + g_ad[d * NH + h];
        v = (v > 0.f) ? v : 0.2f * v;
        g_w[e * NH + h] = v;
        atomicMax(&g_amax[d * NH + h], encf(v));
    }
    atomicAdd(&g_cnt[d], 1);
}

// ---------------- fused: edge exp + denom + CSR scatter ----------------------
__global__ void k_edge_exp_scatter(const int* __restrict__ src, const int* __restrict__ dst)
{
    int e = blockIdx.x * blockDim.x + threadIdx.x;
    if (e >= ET) return;
    int d = (e < EE) ? dst[e] : (e - EE);
    #pragma unroll
    for (int h = 0; h < NH; h++) {
        float m = decf(g_amax[d * NH + h]);
        float w = __expf(g_w[e * NH + h] - m);
        g_w[e * NH + h] = w;
        atomicAdd(&g_den[d * NH + h], w);
    }
    int pos = atomicAdd(&g_cur[d], 1);
    g_csr[pos] = e;
}

// ---------------- exclusive scan of counts ----------------------------------
__global__ __launch_bounds__(1024) void k_scan()
{
    __shared__ int sm[1024];
    const int t = threadIdx.x, base = t * 32;
    int s = 0;
    for (int i = 0; i < 32; i++) s += g_cnt[base + i];
    sm[t] = s;
    __syncthreads();
    for (int o = 1; o < 1024; o <<= 1) {
        int v = (t >= o) ? sm[t - o] : 0;
        __syncthreads();
        sm[t] += v;
        __syncthreads();
    }
    int run = sm[t] - s;
    for (int i = 0; i < 32; i++) {
        g_off[base + i] = run;
        g_cur[base + i] = run;
        run += g_cnt[base + i];
    }
    if (t == 1023) g_off[NN] = sm[1023];
}

// ---------------- x-space aggregation: y[d,h] = sum_e alpha_eh x[src_e] -----
__global__ __launch_bounds__(256)
void k_aggregate_x(const int* __restrict__ src)
{
    const int d = blockIdx.x, t = threadIdx.x;
    const int c0 = t * 2;
    float acc[4][2];
    #pragma unroll
    for (int h = 0; h < 4; h++) { acc[h][0] = 0.f; acc[h][1] = 0.f; }
    const int beg = g_off[d], end = g_off[d + 1];
    for (int p = beg; p < end; p++) {
        int e = g_csr[p];
        int s = (e < EE) ? src[e] : (e - EE);
        float4 w4 = *(const float4*)&g_w[e * NH];
        __nv_bfloat162 xh2 = *(const __nv_bfloat162*)&g_xh[(size_t)s * EMBD + c0];
        __nv_bfloat162 xl2 = *(const __nv_bfloat162*)&g_xl[(size_t)s * EMBD + c0];
        float2 fh = __bfloat1622float2(xh2);
        float2 fl = __bfloat1622float2(xl2);
        float x0 = fh.x + fl.x, x1 = fh.y + fl.y;
        acc[0][0] = fmaf(w4.x, x0, acc[0][0]); acc[0][1] = fmaf(w4.x, x1, acc[0][1]);
        acc[1][0] = fmaf(w4.y, x0, acc[1][0]); acc[1][1] = fmaf(w4.y, x1, acc[1][1]);
        acc[2][0] = fmaf(w4.z, x0, acc[2][0]); acc[2][1] = fmaf(w4.z, x1, acc[2][1]);
        acc[3][0] = fmaf(w4.w, x0, acc[3][0]); acc[3][1] = fmaf(w4.w, x1, acc[3][1]);
    }
    #pragma unroll
    for (int h = 0; h < 4; h++) {
        float dn = 1.f / (g_den[d * NH + h] + 1e-16f);
        __nv_bfloat16 h0, l0, h1, l1;
        split2(acc[h][0] * dn, h0, l0);
        split2(acc[h][1] * dn, h1, l1);
        __nv_bfloat162 hp; hp.x = h0; hp.y = h1;
        __nv_bfloat162 lp; lp.x = l0; lp.y = l1;
        *(__nv_bfloat162*)&g_yh[((size_t)h * NN + d) * EMBD + c0] = hp;
        *(__nv_bfloat162*)&g_yl[((size_t)h * NN + d) * EMBD + c0] = lp;
    }
}

// ---------------- batch segment bounds --------------------------------------
__global__ void k_bstart(const int* __restrict__ batch)
{
    int t = threadIdx.x;
    if (t > NB) return;
    int lo = 0, hi = NN;
    while (lo < hi) { int mid = (lo + hi) >> 1; if (batch[mid] < t) lo = mid + 1; else hi = mid; }
    g_bstart[t] = lo;
}

// ---------------- final MLPs -------------------------------------------------
__global__ __launch_bounds__(256)
void k_mlp(const float* __restrict__ W1r, const float* __restrict__ b1r,
           const float* __restrict__ W2r, const float* __restrict__ b2r,
           const float* __restrict__ W1m, const float* __restrict__ b1m,
           const float* __restrict__ W2m, const float* __restrict__ b2m,
           float* __restrict__ out)
{
    __shared__ float g[4096];
    __shared__ float hid[2][HIDD];
    const int b = blockIdx.x, t = threadIdx.x;
    const float inv = 1.f / fmaxf((float)(g_bstart[b + 1] - g_bstart[b]), 1.f);
    for (int i = t; i < 4096; i += 256) {
        float v;
        if (i < 2048) v = g_pool[b * OUTD + i] * inv;
        else          v = decf(g_pmax[b * OUTD + i - 2048]);
        g[i] = v;
    }
    __syncthreads();
    const int warp = t >> 5, lane = t & 31;
    for (int p = warp; p < 64; p += 8) {
        int task = p >> 5, j = p & 31;
        const float* W1 = task ? W1m : W1r;
        const float* b1 = task ? b1m : b1r;
        float s = 0.f;
        for (int k = lane; k < 4096; k += 32) s = fmaf(g[k], W1[k * HIDD + j], s);
        #pragma unroll
        for (int o = 16; o > 0; o >>= 1) s += __shfl_down_sync(0xffffffff, s, o);
        if (lane == 0) hid[task][j] = fmaxf(s + b1[j], 0.f);
    }
    __syncthreads();
    if (t < 2) {
        const float* W2 = t ? W2m : W2r;
        float o = t ? b2m[0] : b2r[0];
        #pragma unroll
        for (int j = 0; j < HIDD; j++) o = fmaf(hid[t][j], W2[j], o);
        out[t * NB + b] = o;
    }
}

// ---------------- launch -----------------------------------------------------
extern "C" void kernel_launch(void* const* d_in, const int* in_sizes, int n_in,
                              void* d_out, int out_size)
{
    const int*   code  = (const int*)d_in[0];
    const int*   ei    = (const int*)d_in[1];
    const int*   batch = (const int*)d_in[2];
    const float* emb   = (const float*)d_in[3];
    const float* Wf    = (const float*)d_in[4];
    const float* bf    = (const float*)d_in[5];
    const float* Wg    = (const float*)d_in[6];
    const float* atts  = (const float*)d_in[7];
    const float* attd  = (const float*)d_in[8];
    const float* bg    = (const float*)d_in[9];
    const float* W1r   = (const float*)d_in[10];
    const float* b1r   = (const float*)d_in[11];
    const float* W2r   = (const float*)d_in[12];
    const float* b2r   = (const float*)d_in[13];
    const float* W1m   = (const float*)d_in[14];
    const float* b1m   = (const float*)d_in[15];
    const float* W2m   = (const float*)d_in[16];
    const float* b2m   = (const float*)d_in[17];
    float* out = (float*)d_out;

    const int* src = ei;
    const int* dst = ei + EE;

    cudaFuncSetAttribute(k_gemm<1>, cudaFuncAttributeMaxDynamicSharedMemorySize, GEMM_DYN);
    cudaFuncSetAttribute(k_gemm<3>, cudaFuncAttributeMaxDynamicSharedMemorySize, GEMM_DYN);

    __nv_bfloat16 *ah, *al, *xh, *xl, *wfh, *wfl, *wgh, *wgl, *yh, *yl;
    cudaGetSymbolAddress((void**)&ah,  g_ah);
    cudaGetSymbolAddress((void**)&al,  g_al);
    cudaGetSymbolAddress((void**)&xh,  g_xh);
    cudaGetSymbolAddress((void**)&xl,  g_xl);
    cudaGetSymbolAddress((void**)&wfh, g_wfh);
    cudaGetSymbolAddress((void**)&wfl, g_wfl);
    cudaGetSymbolAddress((void**)&wgh, g_wgh);
    cudaGetSymbolAddress((void**)&wgl, g_wgl);
    cudaGetSymbolAddress((void**)&yh,  g_yh);
    cudaGetSymbolAddress((void**)&yl,  g_yl);

    k_init<<<(NN * NH + 255) / 256, 256>>>();
    k_prep_emb<<<NN * 128 / 256, 256>>>(code, emb);
    k_prep_w<<<(EMBD * EMBD + 255) / 256, 256>>>(Wf, wfh, wfl, EMBD);
    k_prep_w<<<(OUTD * EMBD + 255) / 256, 256>>>(Wg, wgh, wgl, OUTD);
    k_prep_att<<<256, 256>>>(Wg, atts, attd);     // 256*8 = 2048 outputs exactly

    // x = emb[code] @ W_feat + b_feat -> split bf16, fused a_src/a_dst dots
    k_gemm<1><<<dim3(EMBD / BN, NN / BM), 256, GEMM_DYN>>>(
        ah, al, wfh, wfl, bf, nullptr, xh, xl);

    k_edge_logits<<<(ET + 255) / 256, 256>>>(src, dst);
    k_scan<<<1, 1024>>>();
    k_edge_exp_scatter<<<(ET + 255) / 256, 256>>>(src, dst);
    k_aggregate_x<<<NN, 256>>>(src);
    k_bstart<<<1, 64>>>(batch);

    // per-head: gat = leaky(y_head @ Wg_head + bias); fused pooling epilogue
    k_gemm<3><<<dim3(512 / BN, NN / BM, NH), 256, GEMM_DYN>>>(
        yh, yl, wgh, wgl, bg, batch, nullptr, nullptr);

    k_mlp<<<NB, 256>>>(W1r, b1r, W2r, b2r, W1m, b1m, W2m, b2m, out);
}

// round 15
// speedup vs baseline: 2.6612x; 1.0166x over previous
#include <cuda_runtime.h>
#include <cuda_bf16.h>
#include <math.h>
#include <cstdint>

#define NN    32768
#define EMBD  512
#define NH    4
#define OUTD  2048
#define EE    131072
#define ET    (EE + NN)     // edges + self loops = 163840
#define NB    32
#define HIDD  32

// GEMM tiling: CTA 128x256, K-step 32, 8 warps (2 row x 4 col), warp tile 64x64
#define BM 128
#define BN 256
#define BK 32
#define KK 512
#define NSTEP (KK / BK)        // 16
// smem: 64B rows (32 bf16), XOR-swizzled 16B chunks: chunk' = chunk ^ ((row>>1)&3)
#define MATA_B (128 * 64)      // 8192 B per A matrix tile
#define MATB_B (256 * 64)      // 16384 B per B matrix tile
#define OFF_AH 0
#define OFF_AL MATA_B
#define OFF_BH (2 * MATA_B)
#define OFF_BL (2 * MATA_B + MATB_B)
#define STAGE_B (2 * MATA_B + 2 * MATB_B)   // 49152
#define GEMM_DYN (3 * STAGE_B)              // 147456 (3-stage)

// ---------------- scratch (device globals; no allocation allowed) ----------
__device__ __nv_bfloat16 g_ah[(size_t)NN * EMBD];   // gathered emb, hi
__device__ __nv_bfloat16 g_al[(size_t)NN * EMBD];   // gathered emb, lo
__device__ __nv_bfloat16 g_xh[(size_t)NN * EMBD];   // x after feat linear, hi
__device__ __nv_bfloat16 g_xl[(size_t)NN * EMBD];
__device__ __nv_bfloat16 g_wfh[EMBD * EMBD];        // W_feat^T  [512,512] K-major
__device__ __nv_bfloat16 g_wfl[EMBD * EMBD];
__device__ __nv_bfloat16 g_wgh[(size_t)OUTD * EMBD];// W_gat^T   [2048,512] K-major
__device__ __nv_bfloat16 g_wgl[(size_t)OUTD * EMBD];
__device__ __nv_bfloat16 g_yh[(size_t)NH * NN * EMBD]; // aggregated x per head, hi
__device__ __nv_bfloat16 g_yl[(size_t)NH * NN * EMBD]; // lo
__device__ float    g_ws[NH * EMBD];                // W_gat_head @ att_src_head
__device__ float    g_wd[NH * EMBD];
__device__ float    g_as [NN * NH];
__device__ float    g_ad [NN * NH];
__device__ unsigned g_amax[NN * NH];
__device__ float    g_den[NN * NH];
__device__ float    g_w  [ET * NH];
__device__ int      g_cnt[NN];
__device__ int      g_off[NN + 1];
__device__ int      g_cur[NN];
__device__ int      g_csr[ET];
__device__ int      g_bstart[NB + 1];
__device__ float    g_pool[NB * OUTD];              // mean-pool sums (atomic)
__device__ unsigned g_pmax[NB * OUTD];              // max-pool, ordered-uint (atomic)

// ---------------- helpers ----------------------------------------------------
__device__ __forceinline__ uint32_t smem_u32(const void* p) {
    uint32_t a;
    asm("{ .reg .u64 t; cvta.to.shared.u64 t, %1; cvt.u32.u64 %0, t; }" : "=r"(a) : "l"(p));
    return a;
}
#define CP16(s, g) \
    asm volatile("cp.async.cg.shared.global [%0], [%1], 16;" :: "r"(s), "l"(g))
#define CP_COMMIT() asm volatile("cp.async.commit_group;" ::: "memory")
#define CP_WAIT2()  asm volatile("cp.async.wait_group 2;" ::: "memory")
#define CP_WAIT1()  asm volatile("cp.async.wait_group 1;" ::: "memory")
#define CP_WAIT0()  asm volatile("cp.async.wait_group 0;" ::: "memory")
#define LDX4(r, a) \
    asm volatile("ldmatrix.sync.aligned.m8n8.x4.shared.b16 {%0,%1,%2,%3}, [%4];" \
        : "=r"((r)[0]), "=r"((r)[1]), "=r"((r)[2]), "=r"((r)[3]) : "r"(a))
#define MMA(d, a, b0, b1) \
    asm volatile("mma.sync.aligned.m16n8k16.row.col.f32.bf16.bf16.f32 " \
        "{%0,%1,%2,%3},{%4,%5,%6,%7},{%8,%9},{%0,%1,%2,%3};" \
        : "+f"((d)[0]), "+f"((d)[1]), "+f"((d)[2]), "+f"((d)[3]) \
        : "r"((a)[0]), "r"((a)[1]), "r"((a)[2]), "r"((a)[3]), "r"(b0), "r"(b1))

// swizzled smem byte offset for (row, 16B-chunk)
__device__ __forceinline__ uint32_t swz(int row, int chunk) {
    return (uint32_t)(row * 64 + ((chunk ^ (row >> 1)) & 3) * 16);
}

__device__ __forceinline__ void split2(float v, __nv_bfloat16& h, __nv_bfloat16& l) {
    h = __float2bfloat16(v);
    l = __float2bfloat16(v - __bfloat162float(h));
}
__device__ __forceinline__ unsigned encf(float f) {
    unsigned u = __float_as_uint(f);
    return (u & 0x80000000u) ? ~u : (u | 0x80000000u);
}
__device__ __forceinline__ float decf(unsigned u) {
    return __uint_as_float((u & 0x80000000u) ? (u ^ 0x80000000u) : ~u);
}
#define ENC_NEGINF 0x007FFFFFu

// ---------------- merged init + emb gather/split (launch #1) -----------------
__global__ __launch_bounds__(256) void k_init_emb(const int* __restrict__ code,
                                                  const float* __restrict__ emb)
{
    int id = blockIdx.x * 256 + threadIdx.x;        // NN*128 ids, 4 elems each
    // init section (first 512 blocks cover all init ranges)
    if (id < NN * NH) { g_amax[id] = ENC_NEGINF; g_den[id] = 0.f; g_as[id] = 0.f; g_ad[id] = 0.f; }
    if (id < NN)      { g_cnt[id] = 0; }
    if (id < NB * OUTD) { g_pool[id] = 0.f; g_pmax[id] = ENC_NEGINF; }
    // emb gather + split
    int m = id >> 7, c4 = (id & 127) << 2;
    float4 v = *(const float4*)&emb[(size_t)code[m] * EMBD + c4];
    __nv_bfloat16 h[4], l[4];
    split2(v.x, h[0], l[0]); split2(v.y, h[1], l[1]);
    split2(v.z, h[2], l[2]); split2(v.w, h[3], l[3]);
    *(uint2*)&g_ah[(size_t)m * EMBD + c4] = *(uint2*)h;
    *(uint2*)&g_al[(size_t)m * EMBD + c4] = *(uint2*)l;
}

// ---------------- prep: W [K=512, Ncols] -> W^T hi/lo [Ncols, 512] ----------
__global__ __launch_bounds__(256) void k_prep_w(const float* __restrict__ W,
                                                __nv_bfloat16* __restrict__ Th,
                                                __nv_bfloat16* __restrict__ Tl, int Ncols)
{
    int id = blockIdx.x * 256 + threadIdx.x;
    if (id >= Ncols * EMBD) return;
    int n = id >> 9, k = id & 511;
    float v = W[(size_t)k * Ncols + n];
    __nv_bfloat16 h, l; split2(v, h, l);
    Th[(size_t)n * EMBD + k] = h;
    Tl[(size_t)n * EMBD + k] = l;
}

// ---------------- prep: w~s[h][k] = sum_c Wg[k, h*512+c]*atts[h,c] ----------
// 2048 outputs total (NH*EMBD); one warp per output.
__global__ __launch_bounds__(256) void k_prep_att(const float* __restrict__ Wg,
                                                  const float* __restrict__ atts,
                                                  const float* __restrict__ attd)
{
    int wid = threadIdx.x >> 5, lane = threadIdx.x & 31;
    int o = blockIdx.x * 8 + wid;          // 2048 outputs
    if (o >= NH * EMBD) return;
    int h = o >> 9, k = o & 511;
    const float* row = Wg + (size_t)k * OUTD + h * EMBD;
    const float* va  = atts + h * EMBD;
    const float* vd  = attd + h * EMBD;
    float ss = 0.f, sd = 0.f;
    #pragma unroll
    for (int c = lane; c < EMBD; c += 32) {
        float w = row[c];
        ss = fmaf(w, va[c], ss);
        sd = fmaf(w, vd[c], sd);
    }
    #pragma unroll
    for (int off = 16; off > 0; off >>= 1) {
        ss += __shfl_down_sync(0xffffffffu, ss, off);
        sd += __shfl_down_sync(0xffffffffu, sd, off);
    }
    if (lane == 0) { g_ws[o] = ss; g_wd[o] = sd; }
}

// ---------------- HMMA split-bf16 GEMM (3-stage cp.async) --------------------
// D[M,N] = (Ah+Al)[M,K] @ (Bh+Bl)^T  where B stored [N,K] K-major
// EPI==1: x-GEMM: out = D + bias -> split bf16 (outH,outL); fused a_src/a_dst
//         dots via g_ws/g_wd (fp32 exact, atomics to g_as/g_ad)
// EPI==3: per-head y-GEMM (blockIdx.z = head): v = leaky(D + bias_gat);
//         fused mean/max pooling into g_pool/g_pmax (nothing else written)
template<int EPI>
__global__ __launch_bounds__(256, 1)
void k_gemm(const __nv_bfloat16* __restrict__ Ah, const __nv_bfloat16* __restrict__ Al,
            const __nv_bfloat16* __restrict__ Bh, const __nv_bfloat16* __restrict__ Bl,
            const float* __restrict__ bias, const int* __restrict__ batch,
            __nv_bfloat16* __restrict__ outH, __nv_bfloat16* __restrict__ outL)
{
    extern __shared__ __align__(128) char sm[];
    __shared__ float s_bias[BN];
    __shared__ float s_ws[4 * BN], s_wd[4 * BN];      // EPI1
    __shared__ float s_as[BM * 4], s_ad[BM * 4];      // EPI1
    __shared__ float s_cs[2 * BN], s_cm[2 * BN];      // EPI3
    __shared__ int   s_batch[BM];                     // EPI3

    const int tid  = threadIdx.x;
    const int lane = tid & 31, wid = tid >> 5;
    const int wr = wid >> 2, wc = wid & 3;         // warp: 64-row block, 64-col block
    const int brow = blockIdx.y * BM;
    const int bcol = blockIdx.x * BN;
    const int head = (EPI == 3) ? blockIdx.z : 0;

    if (EPI == 1) {
        s_bias[tid] = bias[bcol + tid];
        #pragma unroll
        for (int h = 0; h < 4; h++) {
            s_ws[h * BN + tid] = g_ws[h * EMBD + bcol + tid];
            s_wd[h * BN + tid] = g_wd[h * EMBD + bcol + tid];
        }
        #pragma unroll
        for (int i = tid; i < BM * 4; i += 256) { s_as[i] = 0.f; s_ad[i] = 0.f; }
    } else {
        s_bias[tid] = bias[head * 512 + bcol + tid];
    }

    const __nv_bfloat16* Ah_ = Ah + (EPI == 3 ? (size_t)head * NN * KK : 0);
    const __nv_bfloat16* Al_ = Al + (EPI == 3 ? (size_t)head * NN * KK : 0);
    const int bofs = (EPI == 3) ? head * 512 : 0;

    const uint32_t sbase = smem_u32(sm);

    auto load_stage = [&](int st, int k0) {
        const uint32_t so = sbase + st * STAGE_B;
        #pragma unroll
        for (int it = 0; it < 2; it++) {
            int i = tid + it * 256;                 // 512: rows 128 x 4 segs
            int row = i >> 2, seg = i & 3;
            uint32_t sofs = swz(row, seg);
            size_t ga = (size_t)(brow + row) * KK + k0 * BK + seg * 8;
            CP16(so + OFF_AH + sofs, Ah_ + ga);
            CP16(so + OFF_AL + sofs, Al_ + ga);
        }
        #pragma unroll
        for (int it = 0; it < 4; it++) {
            int i = tid + it * 256;                 // 1024: rows 256 x 4 segs
            int row = i >> 2, seg = i & 3;
            uint32_t sofs = swz(row, seg);
            size_t gb = (size_t)(bofs + bcol + row) * KK + k0 * BK + seg * 8;
            CP16(so + OFF_BH + sofs, Bh + gb);
            CP16(so + OFF_BL + sofs, Bl + gb);
        }
    };

    float d[4][8][4];
    #pragma unroll
    for (int mt = 0; mt < 4; mt++)
        #pragma unroll
        for (int nt = 0; nt < 8; nt++)
            #pragma unroll
            for (int j = 0; j < 4; j++) d[mt][nt][j] = 0.f;

    // lane-fixed fragment coordinates
    const int arow = wr * 64 + (lane & 15);
    const int akh  = lane >> 4;                            // A k-half chunk
    const int brow_l = wc * 64 + ((lane >> 4) & 1) * 8 + (lane & 7);
    const int bkh  = (lane >> 3) & 1;                      // B k-half chunk

    load_stage(0, 0); CP_COMMIT();
    load_stage(1, 1); CP_COMMIT();

    int st = 0;
    for (int k0 = 0; k0 < NSTEP; k0++) {
        if (k0 + 2 < NSTEP) {
            int s2 = st + 2; if (s2 >= 3) s2 -= 3;
            load_stage(s2, k0 + 2); CP_COMMIT(); CP_WAIT2();
        } else if (k0 + 1 < NSTEP) CP_WAIT1();
        else CP_WAIT0();
        __syncthreads();

        const uint32_t so = sbase + st * STAGE_B;

        #pragma unroll
        for (int ks = 0; ks < 2; ks++) {
            uint32_t ah[4][4], bh[4][4], xl[4][4];
            #pragma unroll
            for (int mt = 0; mt < 4; mt++) {
                int r = arow + mt * 16;
                LDX4(ah[mt], so + OFF_AH + swz(r, ks * 2 + akh));
            }
            #pragma unroll
            for (int np = 0; np < 4; np++) {
                int r = brow_l + np * 16;
                LDX4(bh[np], so + OFF_BH + swz(r, ks * 2 + bkh));
            }
            #pragma unroll
            for (int mt = 0; mt < 4; mt++)
                #pragma unroll
                for (int nt = 0; nt < 8; nt++)
                    MMA(d[mt][nt], ah[mt], bh[nt >> 1][(nt & 1) * 2], bh[nt >> 1][(nt & 1) * 2 + 1]);
            // Al * Bh
            #pragma unroll
            for (int mt = 0; mt < 4; mt++) {
                int r = arow + mt * 16;
                LDX4(xl[mt], so + OFF_AL + swz(r, ks * 2 + akh));
            }
            #pragma unroll
            for (int mt = 0; mt < 4; mt++)
                #pragma unroll
                for (int nt = 0; nt < 8; nt++)
                    MMA(d[mt][nt], xl[mt], bh[nt >> 1][(nt & 1) * 2], bh[nt >> 1][(nt & 1) * 2 + 1]);
            // Ah * Bl
            #pragma unroll
            for (int np = 0; np < 4; np++) {
                int r = brow_l + np * 16;
                LDX4(xl[np], so + OFF_BL + swz(r, ks * 2 + bkh));
            }
            #pragma unroll
            for (int mt = 0; mt < 4; mt++)
                #pragma unroll
                for (int nt = 0; nt < 8; nt++)
                    MMA(d[mt][nt], ah[mt], xl[nt >> 1][(nt & 1) * 2], xl[nt >> 1][(nt & 1) * 2 + 1]);
        }
        __syncthreads();
        if (++st == 3) st = 0;
    }

    // ---------------- epilogue ----------------
    const int gid = lane >> 2, tig = lane & 3;

    if (EPI == 1) {
        #pragma unroll
        for (int mt = 0; mt < 4; mt++) {
            const int r0 = wr * 64 + mt * 16 + gid;
            float as0[4] = {0,0,0,0}, as1[4] = {0,0,0,0};
            float ad0[4] = {0,0,0,0}, ad1[4] = {0,0,0,0};
            #pragma unroll
            for (int nt = 0; nt < 8; nt++) {
                const int c = wc * 64 + nt * 8 + tig * 2;
                float v0 = d[mt][nt][0] + s_bias[c];
                float v1 = d[mt][nt][1] + s_bias[c + 1];
                float v2 = d[mt][nt][2] + s_bias[c];
                float v3 = d[mt][nt][3] + s_bias[c + 1];
                __nv_bfloat16 h0, l0, h1, l1;
                split2(v0, h0, l0); split2(v1, h1, l1);
                __nv_bfloat162 hp; hp.x = h0; hp.y = h1;
                __nv_bfloat162 lp; lp.x = l0; lp.y = l1;
                *(__nv_bfloat162*)(outH + (size_t)(brow + r0) * EMBD + bcol + c) = hp;
                *(__nv_bfloat162*)(outL + (size_t)(brow + r0) * EMBD + bcol + c) = lp;
                split2(v2, h0, l0); split2(v3, h1, l1);
                hp.x = h0; hp.y = h1; lp.x = l0; lp.y = l1;
                *(__nv_bfloat162*)(outH + (size_t)(brow + r0 + 8) * EMBD + bcol + c) = hp;
                *(__nv_bfloat162*)(outL + (size_t)(brow + r0 + 8) * EMBD + bcol + c) = lp;
                #pragma unroll
                for (int h = 0; h < 4; h++) {
                    float w0 = s_ws[h * BN + c], w1 = s_ws[h * BN + c + 1];
                    float u0 = s_wd[h * BN + c], u1 = s_wd[h * BN + c + 1];
                    as0[h] = fmaf(v0, w0, fmaf(v1, w1, as0[h]));
                    as1[h] = fmaf(v2, w0, fmaf(v3, w1, as1[h]));
                    ad0[h] = fmaf(v0, u0, fmaf(v1, u1, ad0[h]));
                    ad1[h] = fmaf(v2, u0, fmaf(v3, u1, ad1[h]));
                }
            }
            #pragma unroll
            for (int h = 0; h < 4; h++) {
                #pragma unroll
                for (int o = 1; o <= 2; o <<= 1) {
                    as0[h] += __shfl_xor_sync(0xffffffffu, as0[h], o);
                    as1[h] += __shfl_xor_sync(0xffffffffu, as1[h], o);
                    ad0[h] += __shfl_xor_sync(0xffffffffu, ad0[h], o);
                    ad1[h] += __shfl_xor_sync(0xffffffffu, ad1[h], o);
                }
            }
            if (tig == 0) {
                #pragma unroll
                for (int h = 0; h < 4; h++) {
                    atomicAdd(&s_as[r0 * 4 + h], as0[h]);
                    atomicAdd(&s_as[(r0 + 8) * 4 + h], as1[h]);
                    atomicAdd(&s_ad[r0 * 4 + h], ad0[h]);
                    atomicAdd(&s_ad[(r0 + 8) * 4 + h], ad1[h]);
                }
            }
        }
        __syncthreads();
        if (tid < BM) {
            #pragma unroll
            for (int h = 0; h < 4; h++) {
                atomicAdd(&g_as[(brow + tid) * NH + h], s_as[tid * 4 + h]);
                atomicAdd(&g_ad[(brow + tid) * NH + h], s_ad[tid * 4 + h]);
            }
        }
    } else {
        // v = leaky(D + bias) in place
        #pragma unroll
        for (int mt = 0; mt < 4; mt++)
            #pragma unroll
            for (int nt = 0; nt < 8; nt++) {
                const int c = wc * 64 + nt * 8 + tig * 2;
                float v;
                v = d[mt][nt][0] + s_bias[c];     d[mt][nt][0] = (v > 0.f) ? v : 0.01f * v;
                v = d[mt][nt][1] + s_bias[c + 1]; d[mt][nt][1] = (v > 0.f) ? v : 0.01f * v;
                v = d[mt][nt][2] + s_bias[c];     d[mt][nt][2] = (v > 0.f) ? v : 0.01f * v;
                v = d[mt][nt][3] + s_bias[c + 1]; d[mt][nt][3] = (v > 0.f) ? v : 0.01f * v;
            }
        if (tid < BM) s_batch[tid] = batch[brow + tid];
        __syncthreads();
        const int gA = s_batch[0], gB = s_batch[BM - 1];
        const int npass = (gA == gB) ? 1 : 2;     // 128-row tile spans <=2 graphs
        for (int pass = 0; pass < npass; pass++) {
            const int gsel = pass ? gB : gA;
            bool msk[4][2];
            #pragma unroll
            for (int mt = 0; mt < 4; mt++)
                #pragma unroll
                for (int hf = 0; hf < 2; hf++)
                    msk[mt][hf] = (s_batch[wr * 64 + mt * 16 + gid + hf * 8] == gsel);
            #pragma unroll
            for (int nt = 0; nt < 8; nt++) {
                #pragma unroll
                for (int j2 = 0; j2 < 2; j2++) {
                    float sv = 0.f, mv = -INFINITY;
                    #pragma unroll
                    for (int mt = 0; mt < 4; mt++)
                        #pragma unroll
                        for (int hf = 0; hf < 2; hf++) {
                            float v = d[mt][nt][hf * 2 + j2];
                            if (msk[mt][hf]) { sv += v; mv = fmaxf(mv, v); }
                        }
                    #pragma unroll
                    for (int o = 4; o <= 16; o <<= 1) {
                        sv += __shfl_xor_sync(0xffffffffu, sv, o);
                        mv = fmaxf(mv, __shfl_xor_sync(0xffffffffu, mv, o));
                    }
                    if (gid == 0) {
                        int cl = wc * 64 + nt * 8 + tig * 2 + j2;
                        s_cs[wr * BN + cl] = sv;
                        s_cm[wr * BN + cl] = mv;
                    }
                }
            }
            __syncthreads();
            {
                float sv = s_cs[tid] + s_cs[BN + tid];
                float mv = fmaxf(s_cm[tid], s_cm[BN + tid]);
                int colg = head * 512 + bcol + tid;
                atomicAdd(&g_pool[gsel * OUTD + colg], sv);
                atomicMax(&g_pmax[gsel * OUTD + colg], encf(mv));
            }
            __syncthreads();
        }
    }
}

// ---------------- edge logits + segment max + degree counts -----------------
__global__ void k_edge_logits(const int* __restrict__ src, const int* __restrict__ dst)
{
    int e = blockIdx.x * blockDim.x + threadIdx.x;
    if (e >= ET) return;
    int s = (e < EE) ? src[e] : (e - EE);
    int d = (e < EE) ? dst[e] : (e - EE);
    #pragma unroll
    for (int h = 0; h < NH; h++) {
        float v = g_as[s * NH + h] + g_ad[d * NH + h];
        v = (v > 0.f) ? v : 0.2f * v;
        g_w[e * NH + h] = v;
        atomicMax(&g_amax[d * NH + h], encf(v));
    }
    atomicAdd(&g_cnt[d], 1);
}

// ---------------- fused: edge exp + denom + CSR scatter ----------------------
__global__ void k_edge_exp_scatter(const int* __restrict__ src, const int* __restrict__ dst)
{
    int e = blockIdx.x * blockDim.x + threadIdx.x;
    if (e >= ET) return;
    int d = (e < EE) ? dst[e] : (e - EE);
    #pragma unroll
    for (int h = 0; h < NH; h++) {
        float m = decf(g_amax[d * NH + h]);
        float w = __expf(g_w[e * NH + h] - m);
        g_w[e * NH + h] = w;
        atomicAdd(&g_den[d * NH + h], w);
    }
    int pos = atomicAdd(&g_cur[d], 1);
    g_csr[pos] = e;
}

// ---------------- exclusive scan of counts ----------------------------------
__global__ __launch_bounds__(1024) void k_scan()
{
    __shared__ int sm[1024];
    const int t = threadIdx.x, base = t * 32;
    int s = 0;
    for (int i = 0; i < 32; i++) s += g_cnt[base + i];
    sm[t] = s;
    __syncthreads();
    for (int o = 1; o < 1024; o <<= 1) {
        int v = (t >= o) ? sm[t - o] : 0;
        __syncthreads();
        sm[t] += v;
        __syncthreads();
    }
    int run = sm[t] - s;
    for (int i = 0; i < 32; i++) {
        g_off[base + i] = run;
        g_cur[base + i] = run;
        run += g_cnt[base + i];
    }
    if (t == 1023) g_off[NN] = sm[1023];
}

// ---------------- x-space aggregation with smem edge staging ----------------
// y[d,h] = (1/den) sum_e alpha_eh x[src_e]; edges staged 32 at a time to
// break the csr->src->x dependent-latency chain (parallel loads, high MLP).
__global__ __launch_bounds__(256)
void k_aggregate_x(const int* __restrict__ src)
{
    __shared__ int    sh_s[32];
    __shared__ float4 sh_w[32];
    const int d = blockIdx.x, t = threadIdx.x;
    const int c0 = t * 2;
    float acc[4][2];
    #pragma unroll
    for (int h = 0; h < 4; h++) { acc[h][0] = 0.f; acc[h][1] = 0.f; }
    const int beg = g_off[d], end = g_off[d + 1];
    for (int p0 = beg; p0 < end; p0 += 32) {
        const int cnt = min(32, end - p0);
        __syncthreads();
        if (t < cnt) {
            int e = g_csr[p0 + t];
            sh_s[t] = (e < EE) ? src[e] : (e - EE);
            sh_w[t] = *(const float4*)&g_w[e * NH];
        }
        __syncthreads();
        for (int i = 0; i < cnt; i++) {
            int s = sh_s[i];
            float4 w4 = sh_w[i];
            __nv_bfloat162 xh2 = *(const __nv_bfloat162*)&g_xh[(size_t)s * EMBD + c0];
            __nv_bfloat162 xl2 = *(const __nv_bfloat162*)&g_xl[(size_t)s * EMBD + c0];
            float2 fh = __bfloat1622float2(xh2);
            float2 fl = __bfloat1622float2(xl2);
            float x0 = fh.x + fl.x, x1 = fh.y + fl.y;
            acc[0][0] = fmaf(w4.x, x0, acc[0][0]); acc[0][1] = fmaf(w4.x, x1, acc[0][1]);
            acc[1][0] = fmaf(w4.y, x0, acc[1][0]); acc[1][1] = fmaf(w4.y, x1, acc[1][1]);
            acc[2][0] = fmaf(w4.z, x0, acc[2][0]); acc[2][1] = fmaf(w4.z, x1, acc[2][1]);
            acc[3][0] = fmaf(w4.w, x0, acc[3][0]); acc[3][1] = fmaf(w4.w, x1, acc[3][1]);
        }
    }
    #pragma unroll
    for (int h = 0; h < 4; h++) {
        float dn = 1.f / (g_den[d * NH + h] + 1e-16f);
        __nv_bfloat16 h0, l0, h1, l1;
        split2(acc[h][0] * dn, h0, l0);
        split2(acc[h][1] * dn, h1, l1);
        __nv_bfloat162 hp; hp.x = h0; hp.y = h1;
        __nv_bfloat162 lp; lp.x = l0; lp.y = l1;
        *(__nv_bfloat162*)&g_yh[((size_t)h * NN + d) * EMBD + c0] = hp;
        *(__nv_bfloat162*)&g_yl[((size_t)h * NN + d) * EMBD + c0] = lp;
    }
}

// ---------------- batch segment bounds --------------------------------------
__global__ void k_bstart(const int* __restrict__ batch)
{
    int t = threadIdx.x;
    if (t > NB) return;
    int lo = 0, hi = NN;
    while (lo < hi) { int mid = (lo + hi) >> 1; if (batch[mid] < t) lo = mid + 1; else hi = mid; }
    g_bstart[t] = lo;
}

// ---------------- final MLPs -------------------------------------------------
__global__ __launch_bounds__(256)
void k_mlp(const float* __restrict__ W1r, const float* __restrict__ b1r,
           const float* __restrict__ W2r, const float* __restrict__ b2r,
           const float* __restrict__ W1m, const float* __restrict__ b1m,
           const float* __restrict__ W2m, const float* __restrict__ b2m,
           float* __restrict__ out)
{
    __shared__ float g[4096];
    __shared__ float hid[2][HIDD];
    const int b = blockIdx.x, t = threadIdx.x;
    const float inv = 1.f / fmaxf((float)(g_bstart[b + 1] - g_bstart[b]), 1.f);
    for (int i = t; i < 4096; i += 256) {
        float v;
        if (i < 2048) v = g_pool[b * OUTD + i] * inv;
        else          v = decf(g_pmax[b * OUTD + i - 2048]);
        g[i] = v;
    }
    __syncthreads();
    const int warp = t >> 5, lane = t & 31;
    for (int p = warp; p < 64; p += 8) {
        int task = p >> 5, j = p & 31;
        const float* W1 = task ? W1m : W1r;
        const float* b1 = task ? b1m : b1r;
        float s = 0.f;
        for (int k = lane; k < 4096; k += 32) s = fmaf(g[k], W1[k * HIDD + j], s);
        #pragma unroll
        for (int o = 16; o > 0; o >>= 1) s += __shfl_down_sync(0xffffffff, s, o);
        if (lane == 0) hid[task][j] = fmaxf(s + b1[j], 0.f);
    }
    __syncthreads();
    if (t < 2) {
        const float* W2 = t ? W2m : W2r;
        float o = t ? b2m[0] : b2r[0];
        #pragma unroll
        for (int j = 0; j < HIDD; j++) o = fmaf(hid[t][j], W2[j], o);
        out[t * NB + b] = o;
    }
}

// ---------------- launch -----------------------------------------------------
extern "C" void kernel_launch(void* const* d_in, const int* in_sizes, int n_in,
                              void* d_out, int out_size)
{
    const int*   code  = (const int*)d_in[0];
    const int*   ei    = (const int*)d_in[1];
    const int*   batch = (const int*)d_in[2];
    const float* emb   = (const float*)d_in[3];
    const float* Wf    = (const float*)d_in[4];
    const float* bf    = (const float*)d_in[5];
    const float* Wg    = (const float*)d_in[6];
    const float* atts  = (const float*)d_in[7];
    const float* attd  = (const float*)d_in[8];
    const float* bg    = (const float*)d_in[9];
    const float* W1r   = (const float*)d_in[10];
    const float* b1r   = (const float*)d_in[11];
    const float* W2r   = (const float*)d_in[12];
    const float* b2r   = (const float*)d_in[13];
    const float* W1m   = (const float*)d_in[14];
    const float* b1m   = (const float*)d_in[15];
    const float* W2m   = (const float*)d_in[16];
    const float* b2m   = (const float*)d_in[17];
    float* out = (float*)d_out;

    const int* src = ei;
    const int* dst = ei + EE;

    cudaFuncSetAttribute(k_gemm<1>, cudaFuncAttributeMaxDynamicSharedMemorySize, GEMM_DYN);
    cudaFuncSetAttribute(k_gemm<3>, cudaFuncAttributeMaxDynamicSharedMemorySize, GEMM_DYN);

    __nv_bfloat16 *ah, *al, *xh, *xl, *wfh, *wfl, *wgh, *wgl, *yh, *yl;
    cudaGetSymbolAddress((void**)&ah,  g_ah);
    cudaGetSymbolAddress((void**)&al,  g_al);
    cudaGetSymbolAddress((void**)&xh,  g_xh);
    cudaGetSymbolAddress((void**)&xl,  g_xl);
    cudaGetSymbolAddress((void**)&wfh, g_wfh);
    cudaGetSymbolAddress((void**)&wfl, g_wfl);
    cudaGetSymbolAddress((void**)&wgh, g_wgh);
    cudaGetSymbolAddress((void**)&wgl, g_wgl);
    cudaGetSymbolAddress((void**)&yh,  g_yh);
    cudaGetSymbolAddress((void**)&yl,  g_yl);

    // Launch order arranged so the profiler's captured launch (#4) is gemm1.
    k_init_emb<<<NN * 128 / 256, 256>>>(code, emb);                     // 1
    k_prep_w<<<(EMBD * EMBD + 255) / 256, 256>>>(Wf, wfh, wfl, EMBD);   // 2
    k_prep_att<<<256, 256>>>(Wg, atts, attd);                           // 3

    // 4: x = emb[code] @ W_feat + b_feat -> split bf16, fused a_src/a_dst dots
    k_gemm<1><<<dim3(EMBD / BN, NN / BM), 256, GEMM_DYN>>>(
        ah, al, wfh, wfl, bf, nullptr, xh, xl);

    k_prep_w<<<(OUTD * EMBD + 255) / 256, 256>>>(Wg, wgh, wgl, OUTD);   // 5 (needed by gemm3 only)

    k_edge_logits<<<(ET + 255) / 256, 256>>>(src, dst);
    k_scan<<<1, 1024>>>();
    k_edge_exp_scatter<<<(ET + 255) / 256, 256>>>(src, dst);
    k_aggregate_x<<<NN, 256>>>(src);
    k_bstart<<<1, 64>>>(batch);

    // per-head: gat = leaky(y_head @ Wg_head + bias); fused pooling epilogue
    k_gemm<3><<<dim3(512 / BN, NN / BM, NH), 256, GEMM_DYN>>>(
        yh, yl, wgh, wgl, bg, batch, nullptr, nullptr);

    k_mlp<<<NB, 256>>>(W1r, b1r, W2r, b2r, W1m, b1m, W2m, b2m, out);
}